// round 10
// baseline (speedup 1.0000x reference)
#include <cuda_runtime.h>
#include <cuda_bf16.h>
#include <cstdint>

// ===========================================================================
// Problem constants
// ===========================================================================
constexpr int B_   = 2;
constexpr int S_   = 2048;
constexpr int Dm   = 1024;
constexpr int H_   = 16;
constexpr int DK_  = 64;
constexpr int Mrows = B_ * S_;        // 4096
constexpr float ATT_SCALE = 0.125f;   // 1/sqrt(64)

// Scratch (allocation-free: __device__ globals)
__device__ float g_Q[(size_t)Mrows * Dm];
__device__ float g_K[(size_t)Mrows * Dm];   // d-permuted within 8-col blocks
__device__ float g_V[(size_t)Mrows * Dm];
__device__ __nv_bfloat16 g_xh[(size_t)Mrows * Dm];
__device__ __nv_bfloat16 g_xl[(size_t)Mrows * Dm];
__device__ __nv_bfloat16 g_oh[(size_t)Mrows * Dm];
__device__ __nv_bfloat16 g_ol[(size_t)Mrows * Dm];
__device__ __nv_bfloat16 g_wh[(size_t)4 * Dm * Dm];
__device__ __nv_bfloat16 g_wl[(size_t)4 * Dm * Dm];

// ===========================================================================
// mma.sync / ldmatrix / cp.async helpers (legacy tensor path, sm_103 base)
// ===========================================================================
#define MMA_BF16(c, a, b0, b1)                                              \
    asm volatile(                                                           \
        "mma.sync.aligned.m16n8k16.row.col.f32.bf16.bf16.f32 "              \
        "{%0,%1,%2,%3},{%4,%5,%6,%7},{%8,%9},{%0,%1,%2,%3};"                \
        : "+f"((c)[0]), "+f"((c)[1]), "+f"((c)[2]), "+f"((c)[3])            \
        : "r"((a)[0]), "r"((a)[1]), "r"((a)[2]), "r"((a)[3]),               \
          "r"(b0), "r"(b1))

#define MMA_TF32(c, a, b0, b1)                                              \
    asm volatile(                                                           \
        "mma.sync.aligned.m16n8k8.row.col.f32.tf32.tf32.f32 "               \
        "{%0,%1,%2,%3},{%4,%5,%6,%7},{%8,%9},{%0,%1,%2,%3};"                \
        : "+f"((c)[0]), "+f"((c)[1]), "+f"((c)[2]), "+f"((c)[3])            \
        : "r"((a)[0]), "r"((a)[1]), "r"((a)[2]), "r"((a)[3]),               \
          "r"(b0), "r"(b1))

// tf32 MMA where A comes in as raw uint regs (accumulator reinterpret)
#define MMA_TF32F(c, a0, a1, a2, a3, b0, b1)                                \
    asm volatile(                                                           \
        "mma.sync.aligned.m16n8k8.row.col.f32.tf32.tf32.f32 "               \
        "{%0,%1,%2,%3},{%4,%5,%6,%7},{%8,%9},{%0,%1,%2,%3};"                \
        : "+f"((c)[0]), "+f"((c)[1]), "+f"((c)[2]), "+f"((c)[3])            \
        : "r"(a0), "r"(a1), "r"(a2), "r"(a3), "r"(b0), "r"(b1))

#define LDSM4(R, addr)                                                      \
    asm volatile("ldmatrix.sync.aligned.m8n8.x4.shared.b16 "                \
                 "{%0,%1,%2,%3}, [%4];"                                     \
                 : "=r"((R)[0]), "=r"((R)[1]), "=r"((R)[2]), "=r"((R)[3])   \
                 : "r"(addr))

#define LDS64(r0, r1, addr)                                                 \
    asm volatile("ld.shared.v2.b32 {%0, %1}, [%2];"                         \
                 : "=r"(r0), "=r"(r1) : "r"(addr))

#define CP_ASYNC16(dst, src)                                                \
    asm volatile("cp.async.cg.shared.global [%0], [%1], 16;"                \
                 :: "r"(dst), "l"(src))
#define CP_COMMIT() asm volatile("cp.async.commit_group;" ::: "memory")
#define CP_WAIT(n)  asm volatile("cp.async.wait_group %0;" :: "n"(n) : "memory")

__device__ __forceinline__ uint32_t smem_u32(const void* p) {
    uint32_t a;
    asm("{ .reg .u64 t; cvta.to.shared.u64 t, %1; cvt.u32.u64 %0, t; }"
        : "=r"(a) : "l"(p));
    return a;
}
__device__ __forceinline__ uint32_t f2tf(float x) {
    uint32_t r;
    asm("cvt.rna.tf32.f32 %0, %1;" : "=r"(r) : "f"(x));
    return r;
}
__device__ __forceinline__ float u2f(uint32_t x) { return __uint_as_float(x); }
__device__ __forceinline__ uint32_t f_as_u(float x) { return __float_as_uint(x); }

__device__ __forceinline__ uint32_t pack_hi2(float x, float y) {
    __nv_bfloat16 hx = __float2bfloat16_rn(x);
    __nv_bfloat16 hy = __float2bfloat16_rn(y);
    return ((uint32_t)__bfloat16_as_ushort(hy) << 16) | __bfloat16_as_ushort(hx);
}
__device__ __forceinline__ uint32_t pack_lo2(float x, float y) {
    __nv_bfloat16 hx = __float2bfloat16_rn(x);
    __nv_bfloat16 hy = __float2bfloat16_rn(y);
    __nv_bfloat16 lx = __float2bfloat16_rn(x - __bfloat162float(hx));
    __nv_bfloat16 ly = __float2bfloat16_rn(y - __bfloat162float(hy));
    return ((uint32_t)__bfloat16_as_ushort(ly) << 16) | __bfloat16_as_ushort(lx);
}

// ===========================================================================
// Pre-split: fp32 -> bf16 hi + bf16 lo
// ===========================================================================
__global__ __launch_bounds__(256) void split_bf16(const float* __restrict__ in,
                                                  __nv_bfloat16* __restrict__ hi,
                                                  __nv_bfloat16* __restrict__ lo,
                                                  int n4) {
    const int i = blockIdx.x * 256 + threadIdx.x;
    if (i >= n4) return;
    float4 v = ((const float4*)in)[i];
    uint2 ph, pl;
    ph.x = pack_hi2(v.x, v.y);  ph.y = pack_hi2(v.z, v.w);
    pl.x = pack_lo2(v.x, v.y);  pl.y = pack_lo2(v.z, v.w);
    ((uint2*)hi)[i] = ph;
    ((uint2*)lo)[i] = pl;
}

__global__ __launch_bounds__(256) void split_w4(const float* __restrict__ w0,
                                                const float* __restrict__ w1,
                                                const float* __restrict__ w2,
                                                const float* __restrict__ w3,
                                                __nv_bfloat16* __restrict__ hi,
                                                __nv_bfloat16* __restrict__ lo,
                                                int n4each) {
    const int i = blockIdx.x * 256 + threadIdx.x;
    if (i >= 4 * n4each) return;
    const int w = i / n4each, j = i - w * n4each;
    const float* src = (w == 0) ? w0 : (w == 1) ? w1 : (w == 2) ? w2 : w3;
    float4 v = ((const float4*)src)[j];
    uint2 ph, pl;
    ph.x = pack_hi2(v.x, v.y);  ph.y = pack_hi2(v.z, v.w);
    pl.x = pack_lo2(v.x, v.y);  pl.y = pack_lo2(v.z, v.w);
    ((uint2*)hi)[i] = ph;
    ((uint2*)lo)[i] = pl;
}

// ===========================================================================
// GEMM core: 128x128 tile, bf16 3-term split, 3-stage cp.async pipeline,
// one __syncthreads per k-chunk. Optional K d-permuted epilogue:
// within each 8-col block, true col u<4 -> stored at 2u; u>=4 -> 2(u-4)+1.
// ===========================================================================
constexpr int NKC = Dm / 32;          // 32 k-chunks
constexpr int GEMM_SMEM = 3 * 32768;  // 98304

__device__ __forceinline__ uint32_t swaddr(uint32_t base, int row, int ch) {
    return base + row * 64 + (((ch) ^ ((row >> 1) & 3)) << 4);
}

__device__ __forceinline__ void gemm_core(
        const __nv_bfloat16* __restrict__ Ah, const __nv_bfloat16* __restrict__ Al,
        const __nv_bfloat16* __restrict__ Bh, const __nv_bfloat16* __restrict__ Bl,
        float* __restrict__ C, int row0, int col0, uint32_t smb, int kperm) {
    const int tid = threadIdx.x;
    const int lane = tid & 31;
    const int wid = tid >> 5;
    const int wm = (wid >> 2) * 64;
    const int wn = (wid & 3) * 32;
    const int group = lane >> 2, tig = lane & 3;

    float c[4][4][4];
#pragma unroll
    for (int i = 0; i < 4; ++i)
#pragma unroll
        for (int j = 0; j < 4; ++j)
#pragma unroll
            for (int r = 0; r < 4; ++r) c[i][j][r] = 0.f;

    auto issue = [&](int kc, int s) {
        const uint32_t base = smb + s * 32768;
#pragma unroll
        for (int i = 0; i < 2; ++i) {
            const int cidx = tid + i * 256;
            const int row = cidx >> 2, ch = cidx & 3;
            const size_t ga = (size_t)(row0 + row) * Dm + kc * 32 + ch * 8;
            const size_t gb = (size_t)(col0 + row) * Dm + kc * 32 + ch * 8;
            CP_ASYNC16(swaddr(base,         row, ch), Ah + ga);
            CP_ASYNC16(swaddr(base + 8192,  row, ch), Al + ga);
            CP_ASYNC16(swaddr(base + 16384, row, ch), Bh + gb);
            CP_ASYNC16(swaddr(base + 24576, row, ch), Bl + gb);
        }
    };

    issue(0, 0); CP_COMMIT();
    issue(1, 1); CP_COMMIT();

    for (int kc = 0; kc < NKC; ++kc) {
        if (kc + 1 < NKC) { CP_WAIT(1); } else { CP_WAIT(0); }
        __syncthreads();
        if (kc + 2 < NKC) {
            issue(kc + 2, (kc + 2) % 3);
            CP_COMMIT();
        }

        const uint32_t sA = smb + (kc % 3) * 32768;
        const uint32_t sB = sA + 16384;
#pragma unroll
        for (int u = 0; u < 2; ++u) {
            uint32_t bh[8], bl8[8];
#pragma unroll
            for (int p = 0; p < 2; ++p) {
                const int nrow = wn + p * 16 + (lane & 15);
                const int chL = u * 2 + (lane >> 4);
                LDSM4(bh + p * 4,  swaddr(sB,        nrow, chL));
                LDSM4(bl8 + p * 4, swaddr(sB + 8192, nrow, chL));
            }
#pragma unroll
            for (int mt = 0; mt < 4; ++mt) {
                const int mrow = wm + mt * 16 + (lane & 15);
                const int chL = u * 2 + (lane >> 4);
                uint32_t ah[4], alr[4];
                LDSM4(ah,  swaddr(sA,        mrow, chL));
                LDSM4(alr, swaddr(sA + 8192, mrow, chL));
#pragma unroll
                for (int j = 0; j < 4; ++j) {
                    const int p = j >> 1, q = j & 1;
                    MMA_BF16(c[mt][j], ah,  bh[p * 4 + q],  bh[p * 4 + q + 2]);
                    MMA_BF16(c[mt][j], ah,  bl8[p * 4 + q], bl8[p * 4 + q + 2]);
                    MMA_BF16(c[mt][j], alr, bh[p * 4 + q],  bh[p * 4 + q + 2]);
                }
            }
        }
    }

    if (!kperm) {
#pragma unroll
        for (int mt = 0; mt < 4; ++mt) {
#pragma unroll
            for (int j = 0; j < 4; ++j) {
                const int r = row0 + wm + mt * 16 + group;
                const int col = col0 + wn + j * 8 + tig * 2;
                float2 v0 = make_float2(c[mt][j][0], c[mt][j][1]);
                float2 v1 = make_float2(c[mt][j][2], c[mt][j][3]);
                *(float2*)(C + (size_t)r * Dm + col)       = v0;
                *(float2*)(C + (size_t)(r + 8) * Dm + col) = v1;
            }
        }
    } else {
        // d-permuted store for K: u0=2*tig, u1=2*tig+1 within 8-block
        const int u0 = 2 * tig, u1 = 2 * tig + 1;
        const int s0 = (u0 < 4) ? 2 * u0 : 2 * (u0 - 4) + 1;
        const int s1 = (u1 < 4) ? 2 * u1 : 2 * (u1 - 4) + 1;
#pragma unroll
        for (int mt = 0; mt < 4; ++mt) {
#pragma unroll
            for (int j = 0; j < 4; ++j) {
                const int r = row0 + wm + mt * 16 + group;
                const int base = col0 + wn + j * 8;
                C[(size_t)r * Dm + base + s0]       = c[mt][j][0];
                C[(size_t)r * Dm + base + s1]       = c[mt][j][1];
                C[(size_t)(r + 8) * Dm + base + s0] = c[mt][j][2];
                C[(size_t)(r + 8) * Dm + base + s1] = c[mt][j][3];
            }
        }
    }
}

__global__ __launch_bounds__(256, 2) void gemm_qkv(
        const __nv_bfloat16* __restrict__ xh, const __nv_bfloat16* __restrict__ xl,
        const __nv_bfloat16* __restrict__ Wh, const __nv_bfloat16* __restrict__ Wl,
        float* __restrict__ Q, float* __restrict__ K, float* __restrict__ V) {
    extern __shared__ char smc[];
    const int z = blockIdx.z;
    const size_t WN = (size_t)Dm * Dm;
    float* C = (z == 0) ? Q : (z == 1) ? K : V;
    gemm_core(xh, xl, Wh + z * WN, Wl + z * WN, C,
              blockIdx.y * 128, blockIdx.x * 128, smem_u32(smc), z == 1);
}

__global__ __launch_bounds__(256, 2) void gemm_sp(
        const __nv_bfloat16* __restrict__ Ah, const __nv_bfloat16* __restrict__ Al,
        const __nv_bfloat16* __restrict__ Bh, const __nv_bfloat16* __restrict__ Bl,
        float* __restrict__ C) {
    extern __shared__ char smc[];
    gemm_core(Ah, Al, Bh, Bl, C, blockIdx.y * 128, blockIdx.x * 128,
              smem_u32(smc), 0);
}

// ===========================================================================
// Flash attention, tf32 mma.sync, 3-stage cp.async, one barrier per tile.
// K stored d-permuted (by gemm) -> B-fragment pairs adjacent -> lds.64.
//   K stride 72 floats (288B): per half-warp banks 8g+2t, conflict-free.
//   V stride 68 floats: permuted-row scalar reads, conflict-free (8t+g).
// P relayout: S col 2t = PV k t, col 2t+1 = k t+4 (C frag == A frag).
// ===========================================================================
constexpr int FKST = 72, FVST = 68;
constexpr int KTILE_F = 64 * FKST;                  // 4608 floats
constexpr int STAGE_F = KTILE_F + 64 * FVST;        // 8960 floats
constexpr int STAGE_B = STAGE_F * 4;                // 35840 bytes
constexpr int ATT_SMEM = 3 * STAGE_B;               // 107520
constexpr int NT_ = S_ / 64;                        // 32 tiles

__global__ __launch_bounds__(256, 2) void flash_tf32(
        const float* __restrict__ Q, const float* __restrict__ K,
        const float* __restrict__ V,
        __nv_bfloat16* __restrict__ OH, __nv_bfloat16* __restrict__ OL) {
    extern __shared__ float smf[];
    const uint32_t smb = smem_u32(smf);

    const int tid = threadIdx.x;
    const int lane = tid & 31;
    const int wid = tid >> 5;
    const int group = lane >> 2, tig = lane & 3;
    const int q0 = blockIdx.x * 128;
    const int h = blockIdx.y;
    const int b = blockIdx.z;
    const int wb = wid * 16;

    const float* Kb = K + ((size_t)(b * S_)) * Dm + h * DK_;
    const float* Vb = V + ((size_t)(b * S_)) * Dm + h * DK_;

    auto issue = [&](int kt, int s) {
        const uint32_t kbase = smb + s * STAGE_B;
        const uint32_t vbase = kbase + KTILE_F * 4;
#pragma unroll
        for (int i = 0; i < 4; ++i) {
            const int id = tid + i * 256;
            const int r = id >> 4, ch = id & 15;
            const size_t g = (size_t)(kt * 64 + r) * Dm + ch * 4;
            CP_ASYNC16(kbase + r * (FKST * 4) + ch * 16, Kb + g);
            CP_ASYNC16(vbase + r * (FVST * 4) + ch * 16, Vb + g);
        }
    };

    issue(0, 0); CP_COMMIT();
    issue(1, 1); CP_COMMIT();

    // Q fragments (unchanged index math — matches d-permuted K slot order)
    uint32_t qf[8][4];
    {
        const float* Qb = Q + ((size_t)(b * S_ + q0 + wb)) * Dm + h * DK_;
#pragma unroll
        for (int ks = 0; ks < 8; ++ks) {
            const int k0 = ks * 8 + tig;
            qf[ks][0] = f2tf(Qb[(size_t)group * Dm + k0] * ATT_SCALE);
            qf[ks][1] = f2tf(Qb[(size_t)(group + 8) * Dm + k0] * ATT_SCALE);
            qf[ks][2] = f2tf(Qb[(size_t)group * Dm + k0 + 4] * ATT_SCALE);
            qf[ks][3] = f2tf(Qb[(size_t)(group + 8) * Dm + k0 + 4] * ATT_SCALE);
        }
    }

    float of[8][4];
#pragma unroll
    for (int nt = 0; nt < 8; ++nt)
#pragma unroll
        for (int r = 0; r < 4; ++r) of[nt][r] = 0.f;
    float m0 = -1e30f, m1 = -1e30f, l0 = 0.f, l1 = 0.f;

    const uint32_t krow_off = group * (FKST * 4) + tig * 8;  // bytes

    for (int kt = 0; kt < NT_; ++kt) {
        if (kt + 1 < NT_) { CP_WAIT(1); } else { CP_WAIT(0); }
        __syncthreads();
        if (kt + 2 < NT_) {
            issue(kt + 2, (kt + 2) % 3);
            CP_COMMIT();
        }

        const uint32_t ksmb = smb + (kt % 3) * STAGE_B;
        const float* Vsc = smf + (kt % 3) * STAGE_F + KTILE_F;

        // S = Q K^T (16 x 64 per warp); K B-fragment via lds.64
        float sf[8][4];
#pragma unroll
        for (int nt = 0; nt < 8; ++nt)
#pragma unroll
            for (int r = 0; r < 4; ++r) sf[nt][r] = 0.f;
#pragma unroll
        for (int nt = 0; nt < 8; ++nt) {
            const uint32_t rowb = ksmb + nt * (8 * FKST * 4) + krow_off;
#pragma unroll
            for (int ks = 0; ks < 8; ++ks) {
                uint32_t b0, b1;
                LDS64(b0, b1, rowb + ks * 32);
                MMA_TF32(sf[nt], qf[ks], b0, b1);
            }
        }

        // online softmax on fragments
        float mx0 = -1e30f, mx1 = -1e30f;
#pragma unroll
        for (int nt = 0; nt < 8; ++nt) {
            mx0 = fmaxf(mx0, fmaxf(sf[nt][0], sf[nt][1]));
            mx1 = fmaxf(mx1, fmaxf(sf[nt][2], sf[nt][3]));
        }
        mx0 = fmaxf(mx0, __shfl_xor_sync(0xffffffffu, mx0, 1));
        mx0 = fmaxf(mx0, __shfl_xor_sync(0xffffffffu, mx0, 2));
        mx1 = fmaxf(mx1, __shfl_xor_sync(0xffffffffu, mx1, 1));
        mx1 = fmaxf(mx1, __shfl_xor_sync(0xffffffffu, mx1, 2));
        const float M0 = fmaxf(m0, mx0), M1 = fmaxf(m1, mx1);
        const float al0 = __expf(m0 - M0), al1 = __expf(m1 - M1);
        float s0 = 0.f, s1 = 0.f;
#pragma unroll
        for (int nt = 0; nt < 8; ++nt) {
            sf[nt][0] = __expf(sf[nt][0] - M0);
            sf[nt][1] = __expf(sf[nt][1] - M0);
            sf[nt][2] = __expf(sf[nt][2] - M1);
            sf[nt][3] = __expf(sf[nt][3] - M1);
            s0 += sf[nt][0] + sf[nt][1];
            s1 += sf[nt][2] + sf[nt][3];
        }
        s0 += __shfl_xor_sync(0xffffffffu, s0, 1);
        s0 += __shfl_xor_sync(0xffffffffu, s0, 2);
        s1 += __shfl_xor_sync(0xffffffffu, s1, 1);
        s1 += __shfl_xor_sync(0xffffffffu, s1, 2);
        l0 = l0 * al0 + s0;  m0 = M0;
        l1 = l1 * al1 + s1;  m1 = M1;

        // rescale O, then O += P V (C fragment directly reused as A)
#pragma unroll
        for (int nt = 0; nt < 8; ++nt) {
            of[nt][0] *= al0; of[nt][1] *= al0;
            of[nt][2] *= al1; of[nt][3] *= al1;
        }
#pragma unroll
        for (int ks = 0; ks < 8; ++ks) {
            uint32_t pa0 = f2tf(sf[ks][0]);
            uint32_t pa1 = f2tf(sf[ks][2]);
            uint32_t pa2 = f2tf(sf[ks][1]);
            uint32_t pa3 = f2tf(sf[ks][3]);
            const float* v0row = Vsc + (ks * 8 + 2 * tig) * FVST;
            const float* v1row = Vsc + (ks * 8 + 2 * tig + 1) * FVST;
#pragma unroll
            for (int nt = 0; nt < 8; ++nt) {
                const uint32_t b0 = f_as_u(v0row[nt * 8 + group]);
                const uint32_t b1 = f_as_u(v1row[nt * 8 + group]);
                MMA_TF32F(of[nt], pa0, pa1, pa2, pa3, b0, b1);
            }
        }
    }

    // epilogue: write O directly as bf16 hi/lo pairs
    const float i0 = 1.f / l0, i1 = 1.f / l1;
    const size_t base0 = ((size_t)(b * S_ + q0 + wb + group)) * Dm + h * DK_;
    const size_t base1 = ((size_t)(b * S_ + q0 + wb + group + 8)) * Dm + h * DK_;
#pragma unroll
    for (int nt = 0; nt < 8; ++nt) {
        const int col = nt * 8 + tig * 2;
        const float v0 = of[nt][0] * i0, v1 = of[nt][1] * i0;
        const float v2 = of[nt][2] * i1, v3 = of[nt][3] * i1;
        *(uint32_t*)(OH + base0 + col) = pack_hi2(v0, v1);
        *(uint32_t*)(OL + base0 + col) = pack_lo2(v0, v1);
        *(uint32_t*)(OH + base1 + col) = pack_hi2(v2, v3);
        *(uint32_t*)(OL + base1 + col) = pack_lo2(v2, v3);
    }
}

// ===========================================================================
extern "C" void kernel_launch(void* const* d_in, const int* in_sizes, int n_in,
                              void* d_out, int out_size) {
    const float* x  = (const float*)d_in[0];
    const float* Wq = (const float*)d_in[1];
    const float* Wk = (const float*)d_in[2];
    const float* Wv = (const float*)d_in[3];
    const float* Wo = (const float*)d_in[4];
    float* out = (float*)d_out;

    float *Qp, *Kp, *Vp;
    __nv_bfloat16 *xh, *xl, *oh, *ol, *wh, *wl;
    cudaGetSymbolAddress((void**)&Qp, g_Q);
    cudaGetSymbolAddress((void**)&Kp, g_K);
    cudaGetSymbolAddress((void**)&Vp, g_V);
    cudaGetSymbolAddress((void**)&xh, g_xh);
    cudaGetSymbolAddress((void**)&xl, g_xl);
    cudaGetSymbolAddress((void**)&oh, g_oh);
    cudaGetSymbolAddress((void**)&ol, g_ol);
    cudaGetSymbolAddress((void**)&wh, g_wh);
    cudaGetSymbolAddress((void**)&wl, g_wl);

    cudaFuncSetAttribute(gemm_qkv, cudaFuncAttributeMaxDynamicSharedMemorySize,
                         GEMM_SMEM);
    cudaFuncSetAttribute(gemm_sp, cudaFuncAttributeMaxDynamicSharedMemorySize,
                         GEMM_SMEM);
    cudaFuncSetAttribute(flash_tf32, cudaFuncAttributeMaxDynamicSharedMemorySize,
                         ATT_SMEM);

    const size_t WN = (size_t)Dm * Dm;  // 1M elements per W
    const int n4x = (Mrows * Dm) / 4;   // 1M float4
    const int n4w = (int)(WN / 4);      // 256K float4

    split_bf16<<<(n4x + 255) / 256, 256>>>(x, xh, xl, n4x);
    split_w4<<<(4 * n4w + 255) / 256, 256>>>(Wq, Wk, Wv, Wo, wh, wl, n4w);

    const dim3 gQKV(Dm / 128, Mrows / 128, 3);    // (8, 32, 3)
    gemm_qkv<<<gQKV, 256, GEMM_SMEM>>>(xh, xl, wh, wl, Qp, Kp, Vp);

    const dim3 gAttn(S_ / 128, H_, B_);           // (16, 16, 2)
    flash_tf32<<<gAttn, 256, ATT_SMEM>>>(Qp, Kp, Vp, oh, ol);

    const dim3 gProj(Dm / 128, Mrows / 128);      // (8, 32)
    gemm_sp<<<gProj, 256, GEMM_SMEM>>>(oh, ol, wh + 3 * WN, wl + 3 * WN, out);
}

// round 11
// speedup vs baseline: 1.0067x; 1.0067x over previous
#include <cuda_runtime.h>
#include <cuda_bf16.h>
#include <cstdint>

// ===========================================================================
// Problem constants
// ===========================================================================
constexpr int B_   = 2;
constexpr int S_   = 2048;
constexpr int Dm   = 1024;
constexpr int H_   = 16;
constexpr int DK_  = 64;
constexpr int Mrows = B_ * S_;        // 4096
constexpr float ATT_SCALE = 0.125f;   // 1/sqrt(64)

// Scratch (allocation-free: __device__ globals)
__device__ float g_Q[(size_t)Mrows * Dm];
__device__ float g_K[(size_t)Mrows * Dm];   // d-permuted within 8-col blocks
__device__ float g_V[(size_t)Mrows * Dm];
__device__ __nv_bfloat16 g_xh[(size_t)Mrows * Dm];
__device__ __nv_bfloat16 g_xl[(size_t)Mrows * Dm];
__device__ __nv_bfloat16 g_oh[(size_t)Mrows * Dm];
__device__ __nv_bfloat16 g_ol[(size_t)Mrows * Dm];
__device__ __nv_bfloat16 g_wh[(size_t)4 * Dm * Dm];
__device__ __nv_bfloat16 g_wl[(size_t)4 * Dm * Dm];

// ===========================================================================
// mma.sync / ldmatrix / cp.async helpers (legacy tensor path, sm_103 base)
// ===========================================================================
#define MMA_BF16(c, a, b0, b1)                                              \
    asm volatile(                                                           \
        "mma.sync.aligned.m16n8k16.row.col.f32.bf16.bf16.f32 "              \
        "{%0,%1,%2,%3},{%4,%5,%6,%7},{%8,%9},{%0,%1,%2,%3};"                \
        : "+f"((c)[0]), "+f"((c)[1]), "+f"((c)[2]), "+f"((c)[3])            \
        : "r"((a)[0]), "r"((a)[1]), "r"((a)[2]), "r"((a)[3]),               \
          "r"(b0), "r"(b1))

#define MMA_TF32(c, a, b0, b1)                                              \
    asm volatile(                                                           \
        "mma.sync.aligned.m16n8k8.row.col.f32.tf32.tf32.f32 "               \
        "{%0,%1,%2,%3},{%4,%5,%6,%7},{%8,%9},{%0,%1,%2,%3};"                \
        : "+f"((c)[0]), "+f"((c)[1]), "+f"((c)[2]), "+f"((c)[3])            \
        : "r"((a)[0]), "r"((a)[1]), "r"((a)[2]), "r"((a)[3]),               \
          "r"(b0), "r"(b1))

// tf32 MMA where A comes in as raw uint regs (accumulator reinterpret)
#define MMA_TF32F(c, a0, a1, a2, a3, b0, b1)                                \
    asm volatile(                                                           \
        "mma.sync.aligned.m16n8k8.row.col.f32.tf32.tf32.f32 "               \
        "{%0,%1,%2,%3},{%4,%5,%6,%7},{%8,%9},{%0,%1,%2,%3};"                \
        : "+f"((c)[0]), "+f"((c)[1]), "+f"((c)[2]), "+f"((c)[3])            \
        : "r"(a0), "r"(a1), "r"(a2), "r"(a3), "r"(b0), "r"(b1))

#define LDSM4(R, addr)                                                      \
    asm volatile("ldmatrix.sync.aligned.m8n8.x4.shared.b16 "                \
                 "{%0,%1,%2,%3}, [%4];"                                     \
                 : "=r"((R)[0]), "=r"((R)[1]), "=r"((R)[2]), "=r"((R)[3])   \
                 : "r"(addr))

#define CP_ASYNC16(dst, src)                                                \
    asm volatile("cp.async.cg.shared.global [%0], [%1], 16;"                \
                 :: "r"(dst), "l"(src))
#define CP_COMMIT() asm volatile("cp.async.commit_group;" ::: "memory")
#define CP_WAIT(n)  asm volatile("cp.async.wait_group %0;" :: "n"(n) : "memory")

__device__ __forceinline__ uint32_t smem_u32(const void* p) {
    uint32_t a;
    asm("{ .reg .u64 t; cvta.to.shared.u64 t, %1; cvt.u32.u64 %0, t; }"
        : "=r"(a) : "l"(p));
    return a;
}
__device__ __forceinline__ uint32_t f2tf(float x) {
    uint32_t r;
    asm("cvt.rna.tf32.f32 %0, %1;" : "=r"(r) : "f"(x));
    return r;
}
__device__ __forceinline__ float u2f(uint32_t x) { return __uint_as_float(x); }
__device__ __forceinline__ uint32_t f_as_u(float x) { return __float_as_uint(x); }

__device__ __forceinline__ uint32_t pack_hi2(float x, float y) {
    __nv_bfloat16 hx = __float2bfloat16_rn(x);
    __nv_bfloat16 hy = __float2bfloat16_rn(y);
    return ((uint32_t)__bfloat16_as_ushort(hy) << 16) | __bfloat16_as_ushort(hx);
}
__device__ __forceinline__ uint32_t pack_lo2(float x, float y) {
    __nv_bfloat16 hx = __float2bfloat16_rn(x);
    __nv_bfloat16 hy = __float2bfloat16_rn(y);
    __nv_bfloat16 lx = __float2bfloat16_rn(x - __bfloat162float(hx));
    __nv_bfloat16 ly = __float2bfloat16_rn(y - __bfloat162float(hy));
    return ((uint32_t)__bfloat16_as_ushort(ly) << 16) | __bfloat16_as_ushort(lx);
}

// ===========================================================================
// Pre-split: fp32 -> bf16 hi + bf16 lo
// ===========================================================================
__global__ __launch_bounds__(256) void split_bf16(const float* __restrict__ in,
                                                  __nv_bfloat16* __restrict__ hi,
                                                  __nv_bfloat16* __restrict__ lo,
                                                  int n4) {
    const int i = blockIdx.x * 256 + threadIdx.x;
    if (i >= n4) return;
    float4 v = ((const float4*)in)[i];
    uint2 ph, pl;
    ph.x = pack_hi2(v.x, v.y);  ph.y = pack_hi2(v.z, v.w);
    pl.x = pack_lo2(v.x, v.y);  pl.y = pack_lo2(v.z, v.w);
    ((uint2*)hi)[i] = ph;
    ((uint2*)lo)[i] = pl;
}

__global__ __launch_bounds__(256) void split_w4(const float* __restrict__ w0,
                                                const float* __restrict__ w1,
                                                const float* __restrict__ w2,
                                                const float* __restrict__ w3,
                                                __nv_bfloat16* __restrict__ hi,
                                                __nv_bfloat16* __restrict__ lo,
                                                int n4each) {
    const int i = blockIdx.x * 256 + threadIdx.x;
    if (i >= 4 * n4each) return;
    const int w = i / n4each, j = i - w * n4each;
    const float* src = (w == 0) ? w0 : (w == 1) ? w1 : (w == 2) ? w2 : w3;
    float4 v = ((const float4*)src)[j];
    uint2 ph, pl;
    ph.x = pack_hi2(v.x, v.y);  ph.y = pack_hi2(v.z, v.w);
    pl.x = pack_lo2(v.x, v.y);  pl.y = pack_lo2(v.z, v.w);
    ((uint2*)hi)[i] = ph;
    ((uint2*)lo)[i] = pl;
}

// ===========================================================================
// GEMM core: 128x128 tile, bf16 3-term split, 3-stage cp.async pipeline,
// one __syncthreads per k-chunk. Optional K d-permuted epilogue:
// within each 8-col block, true col u<4 -> stored at 2u; u>=4 -> 2(u-4)+1.
// ===========================================================================
constexpr int NKC = Dm / 32;          // 32 k-chunks
constexpr int GEMM_SMEM = 3 * 32768;  // 98304

__device__ __forceinline__ uint32_t swaddr(uint32_t base, int row, int ch) {
    return base + row * 64 + (((ch) ^ ((row >> 1) & 3)) << 4);
}

__device__ __forceinline__ void gemm_core(
        const __nv_bfloat16* __restrict__ Ah, const __nv_bfloat16* __restrict__ Al,
        const __nv_bfloat16* __restrict__ Bh, const __nv_bfloat16* __restrict__ Bl,
        float* __restrict__ C, int row0, int col0, uint32_t smb, int kperm) {
    const int tid = threadIdx.x;
    const int lane = tid & 31;
    const int wid = tid >> 5;
    const int wm = (wid >> 2) * 64;
    const int wn = (wid & 3) * 32;
    const int group = lane >> 2, tig = lane & 3;

    float c[4][4][4];
#pragma unroll
    for (int i = 0; i < 4; ++i)
#pragma unroll
        for (int j = 0; j < 4; ++j)
#pragma unroll
            for (int r = 0; r < 4; ++r) c[i][j][r] = 0.f;

    auto issue = [&](int kc, int s) {
        const uint32_t base = smb + s * 32768;
#pragma unroll
        for (int i = 0; i < 2; ++i) {
            const int cidx = tid + i * 256;
            const int row = cidx >> 2, ch = cidx & 3;
            const size_t ga = (size_t)(row0 + row) * Dm + kc * 32 + ch * 8;
            const size_t gb = (size_t)(col0 + row) * Dm + kc * 32 + ch * 8;
            CP_ASYNC16(swaddr(base,         row, ch), Ah + ga);
            CP_ASYNC16(swaddr(base + 8192,  row, ch), Al + ga);
            CP_ASYNC16(swaddr(base + 16384, row, ch), Bh + gb);
            CP_ASYNC16(swaddr(base + 24576, row, ch), Bl + gb);
        }
    };

    issue(0, 0); CP_COMMIT();
    issue(1, 1); CP_COMMIT();

    for (int kc = 0; kc < NKC; ++kc) {
        if (kc + 1 < NKC) { CP_WAIT(1); } else { CP_WAIT(0); }
        __syncthreads();
        if (kc + 2 < NKC) {
            issue(kc + 2, (kc + 2) % 3);
            CP_COMMIT();
        }

        const uint32_t sA = smb + (kc % 3) * 32768;
        const uint32_t sB = sA + 16384;
#pragma unroll
        for (int u = 0; u < 2; ++u) {
            uint32_t bh[8], bl8[8];
#pragma unroll
            for (int p = 0; p < 2; ++p) {
                const int nrow = wn + p * 16 + (lane & 15);
                const int chL = u * 2 + (lane >> 4);
                LDSM4(bh + p * 4,  swaddr(sB,        nrow, chL));
                LDSM4(bl8 + p * 4, swaddr(sB + 8192, nrow, chL));
            }
#pragma unroll
            for (int mt = 0; mt < 4; ++mt) {
                const int mrow = wm + mt * 16 + (lane & 15);
                const int chL = u * 2 + (lane >> 4);
                uint32_t ah[4], alr[4];
                LDSM4(ah,  swaddr(sA,        mrow, chL));
                LDSM4(alr, swaddr(sA + 8192, mrow, chL));
#pragma unroll
                for (int j = 0; j < 4; ++j) {
                    const int p = j >> 1, q = j & 1;
                    MMA_BF16(c[mt][j], ah,  bh[p * 4 + q],  bh[p * 4 + q + 2]);
                    MMA_BF16(c[mt][j], ah,  bl8[p * 4 + q], bl8[p * 4 + q + 2]);
                    MMA_BF16(c[mt][j], alr, bh[p * 4 + q],  bh[p * 4 + q + 2]);
                }
            }
        }
    }

    if (!kperm) {
#pragma unroll
        for (int mt = 0; mt < 4; ++mt) {
#pragma unroll
            for (int j = 0; j < 4; ++j) {
                const int r = row0 + wm + mt * 16 + group;
                const int col = col0 + wn + j * 8 + tig * 2;
                float2 v0 = make_float2(c[mt][j][0], c[mt][j][1]);
                float2 v1 = make_float2(c[mt][j][2], c[mt][j][3]);
                *(float2*)(C + (size_t)r * Dm + col)       = v0;
                *(float2*)(C + (size_t)(r + 8) * Dm + col) = v1;
            }
        }
    } else {
        // d-permuted store for K: true col u<4 -> 2u ; u>=4 -> 2(u-4)+1
        const int u0 = 2 * tig, u1 = 2 * tig + 1;
        const int s0 = (u0 < 4) ? 2 * u0 : 2 * (u0 - 4) + 1;
        const int s1 = (u1 < 4) ? 2 * u1 : 2 * (u1 - 4) + 1;
#pragma unroll
        for (int mt = 0; mt < 4; ++mt) {
#pragma unroll
            for (int j = 0; j < 4; ++j) {
                const int r = row0 + wm + mt * 16 + group;
                const int base = col0 + wn + j * 8;
                C[(size_t)r * Dm + base + s0]       = c[mt][j][0];
                C[(size_t)r * Dm + base + s1]       = c[mt][j][1];
                C[(size_t)(r + 8) * Dm + base + s0] = c[mt][j][2];
                C[(size_t)(r + 8) * Dm + base + s1] = c[mt][j][3];
            }
        }
    }
}

__global__ __launch_bounds__(256, 2) void gemm_qkv(
        const __nv_bfloat16* __restrict__ xh, const __nv_bfloat16* __restrict__ xl,
        const __nv_bfloat16* __restrict__ Wh, const __nv_bfloat16* __restrict__ Wl,
        float* __restrict__ Q, float* __restrict__ K, float* __restrict__ V) {
    extern __shared__ char smc[];
    const int z = blockIdx.z;
    const size_t WN = (size_t)Dm * Dm;
    float* C = (z == 0) ? Q : (z == 1) ? K : V;
    gemm_core(xh, xl, Wh + z * WN, Wl + z * WN, C,
              blockIdx.y * 128, blockIdx.x * 128, smem_u32(smc), z == 1);
}

__global__ __launch_bounds__(256, 2) void gemm_sp(
        const __nv_bfloat16* __restrict__ Ah, const __nv_bfloat16* __restrict__ Al,
        const __nv_bfloat16* __restrict__ Bh, const __nv_bfloat16* __restrict__ Bl,
        float* __restrict__ C) {
    extern __shared__ char smc[];
    gemm_core(Ah, Al, Bh, Bl, C, blockIdx.y * 128, blockIdx.x * 128,
              smem_u32(smc), 0);
}

// ===========================================================================
// Flash attention, tf32 mma.sync, 3-stage cp.async, one barrier per tile.
// K stored d-permuted -> B-fragment pair adjacent -> plain C++ float2 load
// (compiler-schedulable LDS.64; the R10 asm-volatile version serialized).
//   K stride 72 floats: LDS.64 phases hit all 32 banks once (8g+2t pattern).
//   V stride 68 floats: permuted-row scalar reads, conflict-free.
// P relayout: S col 2t = PV k t, col 2t+1 = k t+4 (C frag == A frag).
// ===========================================================================
constexpr int FKST = 72, FVST = 68;
constexpr int KTILE_F = 64 * FKST;                  // 4608 floats
constexpr int STAGE_F = KTILE_F + 64 * FVST;        // 8960 floats
constexpr int STAGE_B = STAGE_F * 4;                // 35840 bytes
constexpr int ATT_SMEM = 3 * STAGE_B;               // 107520
constexpr int NT_ = S_ / 64;                        // 32 tiles

__global__ __launch_bounds__(256, 2) void flash_tf32(
        const float* __restrict__ Q, const float* __restrict__ K,
        const float* __restrict__ V,
        __nv_bfloat16* __restrict__ OH, __nv_bfloat16* __restrict__ OL) {
    extern __shared__ float smf[];
    const uint32_t smb = smem_u32(smf);

    const int tid = threadIdx.x;
    const int lane = tid & 31;
    const int wid = tid >> 5;
    const int group = lane >> 2, tig = lane & 3;
    const int q0 = blockIdx.x * 128;
    const int h = blockIdx.y;
    const int b = blockIdx.z;
    const int wb = wid * 16;

    const float* Kb = K + ((size_t)(b * S_)) * Dm + h * DK_;
    const float* Vb = V + ((size_t)(b * S_)) * Dm + h * DK_;

    auto issue = [&](int kt, int s) {
        const uint32_t kbase = smb + s * STAGE_B;
        const uint32_t vbase = kbase + KTILE_F * 4;
#pragma unroll
        for (int i = 0; i < 4; ++i) {
            const int id = tid + i * 256;
            const int r = id >> 4, ch = id & 15;
            const size_t g = (size_t)(kt * 64 + r) * Dm + ch * 4;
            CP_ASYNC16(kbase + r * (FKST * 4) + ch * 16, Kb + g);
            CP_ASYNC16(vbase + r * (FVST * 4) + ch * 16, Vb + g);
        }
    };

    issue(0, 0); CP_COMMIT();
    issue(1, 1); CP_COMMIT();

    // Q fragments (true-d indices; matches d-permuted K slot order)
    uint32_t qf[8][4];
    {
        const float* Qb = Q + ((size_t)(b * S_ + q0 + wb)) * Dm + h * DK_;
#pragma unroll
        for (int ks = 0; ks < 8; ++ks) {
            const int k0 = ks * 8 + tig;
            qf[ks][0] = f2tf(Qb[(size_t)group * Dm + k0] * ATT_SCALE);
            qf[ks][1] = f2tf(Qb[(size_t)(group + 8) * Dm + k0] * ATT_SCALE);
            qf[ks][2] = f2tf(Qb[(size_t)group * Dm + k0 + 4] * ATT_SCALE);
            qf[ks][3] = f2tf(Qb[(size_t)(group + 8) * Dm + k0 + 4] * ATT_SCALE);
        }
    }

    float of[8][4];
#pragma unroll
    for (int nt = 0; nt < 8; ++nt)
#pragma unroll
        for (int r = 0; r < 4; ++r) of[nt][r] = 0.f;
    float m0 = -1e30f, m1 = -1e30f, l0 = 0.f, l1 = 0.f;

    for (int kt = 0; kt < NT_; ++kt) {
        if (kt + 1 < NT_) { CP_WAIT(1); } else { CP_WAIT(0); }
        __syncthreads();
        if (kt + 2 < NT_) {
            issue(kt + 2, (kt + 2) % 3);
            CP_COMMIT();
        }

        const float* Ksc = smf + (kt % 3) * STAGE_F;
        const float* Vsc = Ksc + KTILE_F;

        // S = Q K^T (16 x 64 per warp); K pair via schedulable float2 load
        float sf[8][4];
#pragma unroll
        for (int nt = 0; nt < 8; ++nt)
#pragma unroll
            for (int r = 0; r < 4; ++r) sf[nt][r] = 0.f;
#pragma unroll
        for (int nt = 0; nt < 8; ++nt) {
            const float* krow = Ksc + (nt * 8 + group) * FKST + 2 * tig;
#pragma unroll
            for (int ks = 0; ks < 8; ++ks) {
                const float2 kp = *(const float2*)(krow + ks * 8);
                MMA_TF32(sf[nt], qf[ks], f_as_u(kp.x), f_as_u(kp.y));
            }
        }

        // online softmax on fragments
        float mx0 = -1e30f, mx1 = -1e30f;
#pragma unroll
        for (int nt = 0; nt < 8; ++nt) {
            mx0 = fmaxf(mx0, fmaxf(sf[nt][0], sf[nt][1]));
            mx1 = fmaxf(mx1, fmaxf(sf[nt][2], sf[nt][3]));
        }
        mx0 = fmaxf(mx0, __shfl_xor_sync(0xffffffffu, mx0, 1));
        mx0 = fmaxf(mx0, __shfl_xor_sync(0xffffffffu, mx0, 2));
        mx1 = fmaxf(mx1, __shfl_xor_sync(0xffffffffu, mx1, 1));
        mx1 = fmaxf(mx1, __shfl_xor_sync(0xffffffffu, mx1, 2));
        const float M0 = fmaxf(m0, mx0), M1 = fmaxf(m1, mx1);
        const float al0 = __expf(m0 - M0), al1 = __expf(m1 - M1);
        float s0 = 0.f, s1 = 0.f;
#pragma unroll
        for (int nt = 0; nt < 8; ++nt) {
            sf[nt][0] = __expf(sf[nt][0] - M0);
            sf[nt][1] = __expf(sf[nt][1] - M0);
            sf[nt][2] = __expf(sf[nt][2] - M1);
            sf[nt][3] = __expf(sf[nt][3] - M1);
            s0 += sf[nt][0] + sf[nt][1];
            s1 += sf[nt][2] + sf[nt][3];
        }
        s0 += __shfl_xor_sync(0xffffffffu, s0, 1);
        s0 += __shfl_xor_sync(0xffffffffu, s0, 2);
        s1 += __shfl_xor_sync(0xffffffffu, s1, 1);
        s1 += __shfl_xor_sync(0xffffffffu, s1, 2);
        l0 = l0 * al0 + s0;  m0 = M0;
        l1 = l1 * al1 + s1;  m1 = M1;

        // rescale O, then O += P V (C fragment directly reused as A)
#pragma unroll
        for (int nt = 0; nt < 8; ++nt) {
            of[nt][0] *= al0; of[nt][1] *= al0;
            of[nt][2] *= al1; of[nt][3] *= al1;
        }
#pragma unroll
        for (int ks = 0; ks < 8; ++ks) {
            uint32_t pa0 = f2tf(sf[ks][0]);
            uint32_t pa1 = f2tf(sf[ks][2]);
            uint32_t pa2 = f2tf(sf[ks][1]);
            uint32_t pa3 = f2tf(sf[ks][3]);
            const float* v0row = Vsc + (ks * 8 + 2 * tig) * FVST;
            const float* v1row = Vsc + (ks * 8 + 2 * tig + 1) * FVST;
#pragma unroll
            for (int nt = 0; nt < 8; ++nt) {
                const uint32_t b0 = f_as_u(v0row[nt * 8 + group]);
                const uint32_t b1 = f_as_u(v1row[nt * 8 + group]);
                MMA_TF32F(of[nt], pa0, pa1, pa2, pa3, b0, b1);
            }
        }
    }

    // epilogue: write O directly as bf16 hi/lo pairs
    const float i0 = 1.f / l0, i1 = 1.f / l1;
    const size_t base0 = ((size_t)(b * S_ + q0 + wb + group)) * Dm + h * DK_;
    const size_t base1 = ((size_t)(b * S_ + q0 + wb + group + 8)) * Dm + h * DK_;
#pragma unroll
    for (int nt = 0; nt < 8; ++nt) {
        const int col = nt * 8 + tig * 2;
        const float v0 = of[nt][0] * i0, v1 = of[nt][1] * i0;
        const float v2 = of[nt][2] * i1, v3 = of[nt][3] * i1;
        *(uint32_t*)(OH + base0 + col) = pack_hi2(v0, v1);
        *(uint32_t*)(OL + base0 + col) = pack_lo2(v0, v1);
        *(uint32_t*)(OH + base1 + col) = pack_hi2(v2, v3);
        *(uint32_t*)(OL + base1 + col) = pack_lo2(v2, v3);
    }
}

// ===========================================================================
extern "C" void kernel_launch(void* const* d_in, const int* in_sizes, int n_in,
                              void* d_out, int out_size) {
    const float* x  = (const float*)d_in[0];
    const float* Wq = (const float*)d_in[1];
    const float* Wk = (const float*)d_in[2];
    const float* Wv = (const float*)d_in[3];
    const float* Wo = (const float*)d_in[4];
    float* out = (float*)d_out;

    float *Qp, *Kp, *Vp;
    __nv_bfloat16 *xh, *xl, *oh, *ol, *wh, *wl;
    cudaGetSymbolAddress((void**)&Qp, g_Q);
    cudaGetSymbolAddress((void**)&Kp, g_K);
    cudaGetSymbolAddress((void**)&Vp, g_V);
    cudaGetSymbolAddress((void**)&xh, g_xh);
    cudaGetSymbolAddress((void**)&xl, g_xl);
    cudaGetSymbolAddress((void**)&oh, g_oh);
    cudaGetSymbolAddress((void**)&ol, g_ol);
    cudaGetSymbolAddress((void**)&wh, g_wh);
    cudaGetSymbolAddress((void**)&wl, g_wl);

    cudaFuncSetAttribute(gemm_qkv, cudaFuncAttributeMaxDynamicSharedMemorySize,
                         GEMM_SMEM);
    cudaFuncSetAttribute(gemm_sp, cudaFuncAttributeMaxDynamicSharedMemorySize,
                         GEMM_SMEM);
    cudaFuncSetAttribute(flash_tf32, cudaFuncAttributeMaxDynamicSharedMemorySize,
                         ATT_SMEM);

    const size_t WN = (size_t)Dm * Dm;  // 1M elements per W
    const int n4x = (Mrows * Dm) / 4;   // 1M float4
    const int n4w = (int)(WN / 4);      // 256K float4

    split_bf16<<<(n4x + 255) / 256, 256>>>(x, xh, xl, n4x);
    split_w4<<<(4 * n4w + 255) / 256, 256>>>(Wq, Wk, Wv, Wo, wh, wl, n4w);

    const dim3 gQKV(Dm / 128, Mrows / 128, 3);    // (8, 32, 3)
    gemm_qkv<<<gQKV, 256, GEMM_SMEM>>>(xh, xl, wh, wl, Qp, Kp, Vp);

    const dim3 gAttn(S_ / 128, H_, B_);           // (16, 16, 2)
    flash_tf32<<<gAttn, 256, ATT_SMEM>>>(Qp, Kp, Vp, oh, ol);

    const dim3 gProj(Dm / 128, Mrows / 128);      // (8, 32)
    gemm_sp<<<gProj, 256, GEMM_SMEM>>>(oh, ol, wh + 3 * WN, wl + 3 * WN, out);
}

// round 12
// speedup vs baseline: 1.0149x; 1.0081x over previous
#include <cuda_runtime.h>
#include <cuda_bf16.h>
#include <cstdint>

// ===========================================================================
// Problem constants
// ===========================================================================
constexpr int B_   = 2;
constexpr int S_   = 2048;
constexpr int Dm   = 1024;
constexpr int H_   = 16;
constexpr int DK_  = 64;
constexpr int Mrows = B_ * S_;        // 4096
constexpr float ATT_SCALE = 0.125f;   // 1/sqrt(64)

// Scratch (allocation-free: __device__ globals)
__device__ float g_Q[(size_t)Mrows * Dm];
__device__ float g_K[(size_t)Mrows * Dm];
__device__ float g_V[(size_t)Mrows * Dm];
__device__ __nv_bfloat16 g_xh[(size_t)Mrows * Dm];
__device__ __nv_bfloat16 g_xl[(size_t)Mrows * Dm];
__device__ __nv_bfloat16 g_oh[(size_t)Mrows * Dm];
__device__ __nv_bfloat16 g_ol[(size_t)Mrows * Dm];
__device__ __nv_bfloat16 g_wh[(size_t)4 * Dm * Dm];
__device__ __nv_bfloat16 g_wl[(size_t)4 * Dm * Dm];

// ===========================================================================
// mma.sync / ldmatrix / cp.async helpers (legacy tensor path, sm_103 base)
// ===========================================================================
#define MMA_BF16(c, a, b0, b1)                                              \
    asm volatile(                                                           \
        "mma.sync.aligned.m16n8k16.row.col.f32.bf16.bf16.f32 "              \
        "{%0,%1,%2,%3},{%4,%5,%6,%7},{%8,%9},{%0,%1,%2,%3};"                \
        : "+f"((c)[0]), "+f"((c)[1]), "+f"((c)[2]), "+f"((c)[3])            \
        : "r"((a)[0]), "r"((a)[1]), "r"((a)[2]), "r"((a)[3]),               \
          "r"(b0), "r"(b1))

#define MMA_TF32(c, a, b0, b1)                                              \
    asm volatile(                                                           \
        "mma.sync.aligned.m16n8k8.row.col.f32.tf32.tf32.f32 "               \
        "{%0,%1,%2,%3},{%4,%5,%6,%7},{%8,%9},{%0,%1,%2,%3};"                \
        : "+f"((c)[0]), "+f"((c)[1]), "+f"((c)[2]), "+f"((c)[3])            \
        : "r"((a)[0]), "r"((a)[1]), "r"((a)[2]), "r"((a)[3]),               \
          "r"(b0), "r"(b1))

// tf32 MMA where A comes in as raw uint regs (accumulator reinterpret)
#define MMA_TF32F(c, a0, a1, a2, a3, b0, b1)                                \
    asm volatile(                                                           \
        "mma.sync.aligned.m16n8k8.row.col.f32.tf32.tf32.f32 "               \
        "{%0,%1,%2,%3},{%4,%5,%6,%7},{%8,%9},{%0,%1,%2,%3};"                \
        : "+f"((c)[0]), "+f"((c)[1]), "+f"((c)[2]), "+f"((c)[3])            \
        : "r"(a0), "r"(a1), "r"(a2), "r"(a3), "r"(b0), "r"(b1))

#define LDSM4(R, addr)                                                      \
    asm volatile("ldmatrix.sync.aligned.m8n8.x4.shared.b16 "                \
                 "{%0,%1,%2,%3}, [%4];"                                     \
                 : "=r"((R)[0]), "=r"((R)[1]), "=r"((R)[2]), "=r"((R)[3])   \
                 : "r"(addr))

#define CP_ASYNC16(dst, src)                                                \
    asm volatile("cp.async.cg.shared.global [%0], [%1], 16;"                \
                 :: "r"(dst), "l"(src))
#define CP_COMMIT() asm volatile("cp.async.commit_group;" ::: "memory")
#define CP_WAIT(n)  asm volatile("cp.async.wait_group %0;" :: "n"(n) : "memory")

__device__ __forceinline__ uint32_t smem_u32(const void* p) {
    uint32_t a;
    asm("{ .reg .u64 t; cvta.to.shared.u64 t, %1; cvt.u32.u64 %0, t; }"
        : "=r"(a) : "l"(p));
    return a;
}
__device__ __forceinline__ uint32_t f2tf(float x) {
    uint32_t r;
    asm("cvt.rna.tf32.f32 %0, %1;" : "=r"(r) : "f"(x));
    return r;
}
__device__ __forceinline__ float u2f(uint32_t x) { return __uint_as_float(x); }
__device__ __forceinline__ uint32_t f_as_u(float x) { return __float_as_uint(x); }

__device__ __forceinline__ uint32_t pack_hi2(float x, float y) {
    __nv_bfloat16 hx = __float2bfloat16_rn(x);
    __nv_bfloat16 hy = __float2bfloat16_rn(y);
    return ((uint32_t)__bfloat16_as_ushort(hy) << 16) | __bfloat16_as_ushort(hx);
}
__device__ __forceinline__ uint32_t pack_lo2(float x, float y) {
    __nv_bfloat16 hx = __float2bfloat16_rn(x);
    __nv_bfloat16 hy = __float2bfloat16_rn(y);
    __nv_bfloat16 lx = __float2bfloat16_rn(x - __bfloat162float(hx));
    __nv_bfloat16 ly = __float2bfloat16_rn(y - __bfloat162float(hy));
    return ((uint32_t)__bfloat16_as_ushort(ly) << 16) | __bfloat16_as_ushort(lx);
}

// ===========================================================================
// Pre-split: fp32 -> bf16 hi + bf16 lo. 4 float4 per thread (MLP=4).
// ===========================================================================
__global__ __launch_bounds__(256) void split_bf16(const float* __restrict__ in,
                                                  __nv_bfloat16* __restrict__ hi,
                                                  __nv_bfloat16* __restrict__ lo,
                                                  int n4) {
    const int i0 = blockIdx.x * 1024 + threadIdx.x;
    float4 v[4];
#pragma unroll
    for (int k = 0; k < 4; ++k) {
        const int i = i0 + k * 256;
        if (i < n4) v[k] = ((const float4*)in)[i];
    }
#pragma unroll
    for (int k = 0; k < 4; ++k) {
        const int i = i0 + k * 256;
        if (i < n4) {
            uint2 ph, pl;
            ph.x = pack_hi2(v[k].x, v[k].y);  ph.y = pack_hi2(v[k].z, v[k].w);
            pl.x = pack_lo2(v[k].x, v[k].y);  pl.y = pack_lo2(v[k].z, v[k].w);
            ((uint2*)hi)[i] = ph;
            ((uint2*)lo)[i] = pl;
        }
    }
}

__global__ __launch_bounds__(256) void split_w4(const float* __restrict__ w0,
                                                const float* __restrict__ w1,
                                                const float* __restrict__ w2,
                                                const float* __restrict__ w3,
                                                __nv_bfloat16* __restrict__ hi,
                                                __nv_bfloat16* __restrict__ lo,
                                                int n4each) {
    const int i0 = blockIdx.x * 1024 + threadIdx.x;
    const int ntot = 4 * n4each;
    float4 v[4];
#pragma unroll
    for (int k = 0; k < 4; ++k) {
        const int i = i0 + k * 256;
        if (i < ntot) {
            const int w = i / n4each, j = i - w * n4each;
            const float* src = (w == 0) ? w0 : (w == 1) ? w1 : (w == 2) ? w2 : w3;
            v[k] = ((const float4*)src)[j];
        }
    }
#pragma unroll
    for (int k = 0; k < 4; ++k) {
        const int i = i0 + k * 256;
        if (i < ntot) {
            uint2 ph, pl;
            ph.x = pack_hi2(v[k].x, v[k].y);  ph.y = pack_hi2(v[k].z, v[k].w);
            pl.x = pack_lo2(v[k].x, v[k].y);  pl.y = pack_lo2(v[k].z, v[k].w);
            ((uint2*)hi)[i] = ph;
            ((uint2*)lo)[i] = pl;
        }
    }
}

// ===========================================================================
// GEMM core: 128x128 tile, bf16 3-term split, 3-stage cp.async pipeline,
// one __syncthreads per k-chunk (R9/R8 version, plain float2 epilogue).
// ===========================================================================
constexpr int NKC = Dm / 32;          // 32 k-chunks
constexpr int GEMM_SMEM = 3 * 32768;  // 98304

__device__ __forceinline__ uint32_t swaddr(uint32_t base, int row, int ch) {
    return base + row * 64 + (((ch) ^ ((row >> 1) & 3)) << 4);
}

__device__ __forceinline__ void gemm_core(
        const __nv_bfloat16* __restrict__ Ah, const __nv_bfloat16* __restrict__ Al,
        const __nv_bfloat16* __restrict__ Bh, const __nv_bfloat16* __restrict__ Bl,
        float* __restrict__ C, int row0, int col0, uint32_t smb) {
    const int tid = threadIdx.x;
    const int lane = tid & 31;
    const int wid = tid >> 5;
    const int wm = (wid >> 2) * 64;
    const int wn = (wid & 3) * 32;
    const int group = lane >> 2, tig = lane & 3;

    float c[4][4][4];
#pragma unroll
    for (int i = 0; i < 4; ++i)
#pragma unroll
        for (int j = 0; j < 4; ++j)
#pragma unroll
            for (int r = 0; r < 4; ++r) c[i][j][r] = 0.f;

    auto issue = [&](int kc, int s) {
        const uint32_t base = smb + s * 32768;
#pragma unroll
        for (int i = 0; i < 2; ++i) {
            const int cidx = tid + i * 256;
            const int row = cidx >> 2, ch = cidx & 3;
            const size_t ga = (size_t)(row0 + row) * Dm + kc * 32 + ch * 8;
            const size_t gb = (size_t)(col0 + row) * Dm + kc * 32 + ch * 8;
            CP_ASYNC16(swaddr(base,         row, ch), Ah + ga);
            CP_ASYNC16(swaddr(base + 8192,  row, ch), Al + ga);
            CP_ASYNC16(swaddr(base + 16384, row, ch), Bh + gb);
            CP_ASYNC16(swaddr(base + 24576, row, ch), Bl + gb);
        }
    };

    issue(0, 0); CP_COMMIT();
    issue(1, 1); CP_COMMIT();

    for (int kc = 0; kc < NKC; ++kc) {
        if (kc + 1 < NKC) { CP_WAIT(1); } else { CP_WAIT(0); }
        __syncthreads();
        if (kc + 2 < NKC) {
            issue(kc + 2, (kc + 2) % 3);
            CP_COMMIT();
        }

        const uint32_t sA = smb + (kc % 3) * 32768;
        const uint32_t sB = sA + 16384;
#pragma unroll
        for (int u = 0; u < 2; ++u) {
            uint32_t bh[8], bl8[8];
#pragma unroll
            for (int p = 0; p < 2; ++p) {
                const int nrow = wn + p * 16 + (lane & 15);
                const int chL = u * 2 + (lane >> 4);
                LDSM4(bh + p * 4,  swaddr(sB,        nrow, chL));
                LDSM4(bl8 + p * 4, swaddr(sB + 8192, nrow, chL));
            }
#pragma unroll
            for (int mt = 0; mt < 4; ++mt) {
                const int mrow = wm + mt * 16 + (lane & 15);
                const int chL = u * 2 + (lane >> 4);
                uint32_t ah[4], alr[4];
                LDSM4(ah,  swaddr(sA,        mrow, chL));
                LDSM4(alr, swaddr(sA + 8192, mrow, chL));
#pragma unroll
                for (int j = 0; j < 4; ++j) {
                    const int p = j >> 1, q = j & 1;
                    MMA_BF16(c[mt][j], ah,  bh[p * 4 + q],  bh[p * 4 + q + 2]);
                    MMA_BF16(c[mt][j], ah,  bl8[p * 4 + q], bl8[p * 4 + q + 2]);
                    MMA_BF16(c[mt][j], alr, bh[p * 4 + q],  bh[p * 4 + q + 2]);
                }
            }
        }
    }

#pragma unroll
    for (int mt = 0; mt < 4; ++mt) {
#pragma unroll
        for (int j = 0; j < 4; ++j) {
            const int r = row0 + wm + mt * 16 + group;
            const int col = col0 + wn + j * 8 + tig * 2;
            float2 v0 = make_float2(c[mt][j][0], c[mt][j][1]);
            float2 v1 = make_float2(c[mt][j][2], c[mt][j][3]);
            *(float2*)(C + (size_t)r * Dm + col)       = v0;
            *(float2*)(C + (size_t)(r + 8) * Dm + col) = v1;
        }
    }
}

__global__ __launch_bounds__(256, 2) void gemm_qkv(
        const __nv_bfloat16* __restrict__ xh, const __nv_bfloat16* __restrict__ xl,
        const __nv_bfloat16* __restrict__ Wh, const __nv_bfloat16* __restrict__ Wl,
        float* __restrict__ Q, float* __restrict__ K, float* __restrict__ V) {
    extern __shared__ char smc[];
    const int z = blockIdx.z;
    const size_t WN = (size_t)Dm * Dm;
    float* C = (z == 0) ? Q : (z == 1) ? K : V;
    gemm_core(xh, xl, Wh + z * WN, Wl + z * WN, C,
              blockIdx.y * 128, blockIdx.x * 128, smem_u32(smc));
}

__global__ __launch_bounds__(256, 2) void gemm_sp(
        const __nv_bfloat16* __restrict__ Ah, const __nv_bfloat16* __restrict__ Al,
        const __nv_bfloat16* __restrict__ Bh, const __nv_bfloat16* __restrict__ Bl,
        float* __restrict__ C) {
    extern __shared__ char smc[];
    gemm_core(Ah, Al, Bh, Bl, C, blockIdx.y * 128, blockIdx.x * 128,
              smem_u32(smc));
}

// ===========================================================================
// Flash attention (exact R9-best version): tf32 mma.sync, 3-stage cp.async,
// one barrier per tile, shuffle-free P relayout (S col 2t = PV k t,
// col 2t+1 = k t+4; C fragment == A fragment; V rows read permuted).
// K stride 68, V stride 68, normal (unpermuted) K layout, scalar LDS.
// ===========================================================================
constexpr int FST = 68;
constexpr int FTILE_B = 64 * FST * 4 * 2;          // 34816 bytes per stage
constexpr int ATT_SMEM = 3 * FTILE_B;              // 104448
constexpr int NT_ = S_ / 64;                       // 32 tiles

__global__ __launch_bounds__(256, 2) void flash_tf32(
        const float* __restrict__ Q, const float* __restrict__ K,
        const float* __restrict__ V,
        __nv_bfloat16* __restrict__ OH, __nv_bfloat16* __restrict__ OL) {
    extern __shared__ float smf[];
    const uint32_t smb = smem_u32(smf);

    const int tid = threadIdx.x;
    const int lane = tid & 31;
    const int wid = tid >> 5;
    const int group = lane >> 2, tig = lane & 3;
    const int q0 = blockIdx.x * 128;
    const int h = blockIdx.y;
    const int b = blockIdx.z;
    const int wb = wid * 16;

    const float* Kb = K + ((size_t)(b * S_)) * Dm + h * DK_;
    const float* Vb = V + ((size_t)(b * S_)) * Dm + h * DK_;

    auto issue = [&](int kt, int s) {
        const uint32_t kbase = smb + s * FTILE_B;
        const uint32_t vbase = kbase + 64 * FST * 4;
#pragma unroll
        for (int i = 0; i < 4; ++i) {
            const int id = tid + i * 256;
            const int r = id >> 4, ch = id & 15;
            const size_t g = (size_t)(kt * 64 + r) * Dm + ch * 4;
            CP_ASYNC16(kbase + r * (FST * 4) + ch * 16, Kb + g);
            CP_ASYNC16(vbase + r * (FST * 4) + ch * 16, Vb + g);
        }
    };

    issue(0, 0); CP_COMMIT();
    issue(1, 1); CP_COMMIT();

    uint32_t qf[8][4];
    {
        const float* Qb = Q + ((size_t)(b * S_ + q0 + wb)) * Dm + h * DK_;
#pragma unroll
        for (int ks = 0; ks < 8; ++ks) {
            const int k0 = ks * 8 + tig;
            qf[ks][0] = f2tf(Qb[(size_t)group * Dm + k0] * ATT_SCALE);
            qf[ks][1] = f2tf(Qb[(size_t)(group + 8) * Dm + k0] * ATT_SCALE);
            qf[ks][2] = f2tf(Qb[(size_t)group * Dm + k0 + 4] * ATT_SCALE);
            qf[ks][3] = f2tf(Qb[(size_t)(group + 8) * Dm + k0 + 4] * ATT_SCALE);
        }
    }

    float of[8][4];
#pragma unroll
    for (int nt = 0; nt < 8; ++nt)
#pragma unroll
        for (int r = 0; r < 4; ++r) of[nt][r] = 0.f;
    float m0 = -1e30f, m1 = -1e30f, l0 = 0.f, l1 = 0.f;

    for (int kt = 0; kt < NT_; ++kt) {
        if (kt + 1 < NT_) { CP_WAIT(1); } else { CP_WAIT(0); }
        __syncthreads();
        if (kt + 2 < NT_) {
            issue(kt + 2, (kt + 2) % 3);
            CP_COMMIT();
        }

        const float* Ksc = smf + (kt % 3) * (FTILE_B / 4);
        const float* Vsc = Ksc + 64 * FST;

        // S = Q K^T (16 x 64 per warp)
        float sf[8][4];
#pragma unroll
        for (int nt = 0; nt < 8; ++nt)
#pragma unroll
            for (int r = 0; r < 4; ++r) sf[nt][r] = 0.f;
#pragma unroll
        for (int nt = 0; nt < 8; ++nt) {
            const float* krow = Ksc + (nt * 8 + group) * FST;
#pragma unroll
            for (int ks = 0; ks < 8; ++ks) {
                const uint32_t b0 = f_as_u(krow[ks * 8 + tig]);
                const uint32_t b1 = f_as_u(krow[ks * 8 + tig + 4]);
                MMA_TF32(sf[nt], qf[ks], b0, b1);
            }
        }

        // online softmax on fragments (column order irrelevant)
        float mx0 = -1e30f, mx1 = -1e30f;
#pragma unroll
        for (int nt = 0; nt < 8; ++nt) {
            mx0 = fmaxf(mx0, fmaxf(sf[nt][0], sf[nt][1]));
            mx1 = fmaxf(mx1, fmaxf(sf[nt][2], sf[nt][3]));
        }
        mx0 = fmaxf(mx0, __shfl_xor_sync(0xffffffffu, mx0, 1));
        mx0 = fmaxf(mx0, __shfl_xor_sync(0xffffffffu, mx0, 2));
        mx1 = fmaxf(mx1, __shfl_xor_sync(0xffffffffu, mx1, 1));
        mx1 = fmaxf(mx1, __shfl_xor_sync(0xffffffffu, mx1, 2));
        const float M0 = fmaxf(m0, mx0), M1 = fmaxf(m1, mx1);
        const float al0 = __expf(m0 - M0), al1 = __expf(m1 - M1);
        float s0 = 0.f, s1 = 0.f;
#pragma unroll
        for (int nt = 0; nt < 8; ++nt) {
            sf[nt][0] = __expf(sf[nt][0] - M0);
            sf[nt][1] = __expf(sf[nt][1] - M0);
            sf[nt][2] = __expf(sf[nt][2] - M1);
            sf[nt][3] = __expf(sf[nt][3] - M1);
            s0 += sf[nt][0] + sf[nt][1];
            s1 += sf[nt][2] + sf[nt][3];
        }
        s0 += __shfl_xor_sync(0xffffffffu, s0, 1);
        s0 += __shfl_xor_sync(0xffffffffu, s0, 2);
        s1 += __shfl_xor_sync(0xffffffffu, s1, 1);
        s1 += __shfl_xor_sync(0xffffffffu, s1, 2);
        l0 = l0 * al0 + s0;  m0 = M0;
        l1 = l1 * al1 + s1;  m1 = M1;

        // rescale O, then O += P V (C fragment directly reused as A)
#pragma unroll
        for (int nt = 0; nt < 8; ++nt) {
            of[nt][0] *= al0; of[nt][1] *= al0;
            of[nt][2] *= al1; of[nt][3] *= al1;
        }
#pragma unroll
        for (int ks = 0; ks < 8; ++ks) {
            uint32_t pa0 = f2tf(sf[ks][0]);
            uint32_t pa1 = f2tf(sf[ks][2]);
            uint32_t pa2 = f2tf(sf[ks][1]);
            uint32_t pa3 = f2tf(sf[ks][3]);
            const float* v0row = Vsc + (ks * 8 + 2 * tig) * FST;
            const float* v1row = Vsc + (ks * 8 + 2 * tig + 1) * FST;
#pragma unroll
            for (int nt = 0; nt < 8; ++nt) {
                const uint32_t b0 = f_as_u(v0row[nt * 8 + group]);
                const uint32_t b1 = f_as_u(v1row[nt * 8 + group]);
                MMA_TF32F(of[nt], pa0, pa1, pa2, pa3, b0, b1);
            }
        }
    }

    // epilogue: write O directly as bf16 hi/lo pairs
    const float i0 = 1.f / l0, i1 = 1.f / l1;
    const size_t base0 = ((size_t)(b * S_ + q0 + wb + group)) * Dm + h * DK_;
    const size_t base1 = ((size_t)(b * S_ + q0 + wb + group + 8)) * Dm + h * DK_;
#pragma unroll
    for (int nt = 0; nt < 8; ++nt) {
        const int col = nt * 8 + tig * 2;
        const float v0 = of[nt][0] * i0, v1 = of[nt][1] * i0;
        const float v2 = of[nt][2] * i1, v3 = of[nt][3] * i1;
        *(uint32_t*)(OH + base0 + col) = pack_hi2(v0, v1);
        *(uint32_t*)(OL + base0 + col) = pack_lo2(v0, v1);
        *(uint32_t*)(OH + base1 + col) = pack_hi2(v2, v3);
        *(uint32_t*)(OL + base1 + col) = pack_lo2(v2, v3);
    }
}

// ===========================================================================
extern "C" void kernel_launch(void* const* d_in, const int* in_sizes, int n_in,
                              void* d_out, int out_size) {
    const float* x  = (const float*)d_in[0];
    const float* Wq = (const float*)d_in[1];
    const float* Wk = (const float*)d_in[2];
    const float* Wv = (const float*)d_in[3];
    const float* Wo = (const float*)d_in[4];
    float* out = (float*)d_out;

    float *Qp, *Kp, *Vp;
    __nv_bfloat16 *xh, *xl, *oh, *ol, *wh, *wl;
    cudaGetSymbolAddress((void**)&Qp, g_Q);
    cudaGetSymbolAddress((void**)&Kp, g_K);
    cudaGetSymbolAddress((void**)&Vp, g_V);
    cudaGetSymbolAddress((void**)&xh, g_xh);
    cudaGetSymbolAddress((void**)&xl, g_xl);
    cudaGetSymbolAddress((void**)&oh, g_oh);
    cudaGetSymbolAddress((void**)&ol, g_ol);
    cudaGetSymbolAddress((void**)&wh, g_wh);
    cudaGetSymbolAddress((void**)&wl, g_wl);

    cudaFuncSetAttribute(gemm_qkv, cudaFuncAttributeMaxDynamicSharedMemorySize,
                         GEMM_SMEM);
    cudaFuncSetAttribute(gemm_sp, cudaFuncAttributeMaxDynamicSharedMemorySize,
                         GEMM_SMEM);
    cudaFuncSetAttribute(flash_tf32, cudaFuncAttributeMaxDynamicSharedMemorySize,
                         ATT_SMEM);

    const size_t WN = (size_t)Dm * Dm;  // 1M elements per W
    const int n4x = (Mrows * Dm) / 4;   // 1M float4
    const int n4w = (int)(WN / 4);      // 256K float4

    split_bf16<<<(n4x + 1023) / 1024, 256>>>(x, xh, xl, n4x);
    split_w4<<<(4 * n4w + 1023) / 1024, 256>>>(Wq, Wk, Wv, Wo, wh, wl, n4w);

    const dim3 gQKV(Dm / 128, Mrows / 128, 3);    // (8, 32, 3)
    gemm_qkv<<<gQKV, 256, GEMM_SMEM>>>(xh, xl, wh, wl, Qp, Kp, Vp);

    const dim3 gAttn(S_ / 128, H_, B_);           // (16, 16, 2)
    flash_tf32<<<gAttn, 256, ATT_SMEM>>>(Qp, Kp, Vp, oh, ol);

    const dim3 gProj(Dm / 128, Mrows / 128);      // (8, 32)
    gemm_sp<<<gProj, 256, GEMM_SMEM>>>(oh, ol, wh + 3 * WN, wl + 3 * WN, out);
}

// round 13
// speedup vs baseline: 1.0689x; 1.0531x over previous
#include <cuda_runtime.h>
#include <cuda_bf16.h>
#include <cstdint>

// ===========================================================================
// Problem constants
// ===========================================================================
constexpr int B_   = 2;
constexpr int S_   = 2048;
constexpr int Dm   = 1024;
constexpr int H_   = 16;
constexpr int DK_  = 64;
constexpr int Mrows = B_ * S_;        // 4096
constexpr float ATT_SCALE = 0.125f;   // 1/sqrt(64)

// Scratch (allocation-free: __device__ globals)
__device__ float g_Q[(size_t)Mrows * Dm];
__device__ float g_K[(size_t)Mrows * Dm];
__device__ float g_V[(size_t)Mrows * Dm];
__device__ __nv_bfloat16 g_xh[(size_t)Mrows * Dm];
__device__ __nv_bfloat16 g_xl[(size_t)Mrows * Dm];
__device__ __nv_bfloat16 g_oh[(size_t)Mrows * Dm];
__device__ __nv_bfloat16 g_ol[(size_t)Mrows * Dm];
__device__ __nv_bfloat16 g_wh[(size_t)4 * Dm * Dm];
__device__ __nv_bfloat16 g_wl[(size_t)4 * Dm * Dm];

// ===========================================================================
// mma.sync / ldmatrix / cp.async helpers (legacy tensor path, sm_103 base)
// ===========================================================================
#define MMA_BF16(c, a, b0, b1)                                              \
    asm volatile(                                                           \
        "mma.sync.aligned.m16n8k16.row.col.f32.bf16.bf16.f32 "              \
        "{%0,%1,%2,%3},{%4,%5,%6,%7},{%8,%9},{%0,%1,%2,%3};"                \
        : "+f"((c)[0]), "+f"((c)[1]), "+f"((c)[2]), "+f"((c)[3])            \
        : "r"((a)[0]), "r"((a)[1]), "r"((a)[2]), "r"((a)[3]),               \
          "r"(b0), "r"(b1))

#define MMA_TF32(c, a, b0, b1)                                              \
    asm volatile(                                                           \
        "mma.sync.aligned.m16n8k8.row.col.f32.tf32.tf32.f32 "               \
        "{%0,%1,%2,%3},{%4,%5,%6,%7},{%8,%9},{%0,%1,%2,%3};"                \
        : "+f"((c)[0]), "+f"((c)[1]), "+f"((c)[2]), "+f"((c)[3])            \
        : "r"((a)[0]), "r"((a)[1]), "r"((a)[2]), "r"((a)[3]),               \
          "r"(b0), "r"(b1))

// tf32 MMA where A comes in as raw uint regs (accumulator reinterpret)
#define MMA_TF32F(c, a0, a1, a2, a3, b0, b1)                                \
    asm volatile(                                                           \
        "mma.sync.aligned.m16n8k8.row.col.f32.tf32.tf32.f32 "               \
        "{%0,%1,%2,%3},{%4,%5,%6,%7},{%8,%9},{%0,%1,%2,%3};"                \
        : "+f"((c)[0]), "+f"((c)[1]), "+f"((c)[2]), "+f"((c)[3])            \
        : "r"(a0), "r"(a1), "r"(a2), "r"(a3), "r"(b0), "r"(b1))

#define LDSM4(R, addr)                                                      \
    asm volatile("ldmatrix.sync.aligned.m8n8.x4.shared.b16 "                \
                 "{%0,%1,%2,%3}, [%4];"                                     \
                 : "=r"((R)[0]), "=r"((R)[1]), "=r"((R)[2]), "=r"((R)[3])   \
                 : "r"(addr))

#define CP_ASYNC16(dst, src)                                                \
    asm volatile("cp.async.cg.shared.global [%0], [%1], 16;"                \
                 :: "r"(dst), "l"(src))
#define CP_COMMIT() asm volatile("cp.async.commit_group;" ::: "memory")
#define CP_WAIT(n)  asm volatile("cp.async.wait_group %0;" :: "n"(n) : "memory")

__device__ __forceinline__ uint32_t smem_u32(const void* p) {
    uint32_t a;
    asm("{ .reg .u64 t; cvta.to.shared.u64 t, %1; cvt.u32.u64 %0, t; }"
        : "=r"(a) : "l"(p));
    return a;
}
__device__ __forceinline__ uint32_t f2tf(float x) {
    uint32_t r;
    asm("cvt.rna.tf32.f32 %0, %1;" : "=r"(r) : "f"(x));
    return r;
}
__device__ __forceinline__ float u2f(uint32_t x) { return __uint_as_float(x); }
__device__ __forceinline__ uint32_t f_as_u(float x) { return __float_as_uint(x); }

__device__ __forceinline__ uint32_t pack_hi2(float x, float y) {
    __nv_bfloat16 hx = __float2bfloat16_rn(x);
    __nv_bfloat16 hy = __float2bfloat16_rn(y);
    return ((uint32_t)__bfloat16_as_ushort(hy) << 16) | __bfloat16_as_ushort(hx);
}
__device__ __forceinline__ uint32_t pack_lo2(float x, float y) {
    __nv_bfloat16 hx = __float2bfloat16_rn(x);
    __nv_bfloat16 hy = __float2bfloat16_rn(y);
    __nv_bfloat16 lx = __float2bfloat16_rn(x - __bfloat162float(hx));
    __nv_bfloat16 ly = __float2bfloat16_rn(y - __bfloat162float(hy));
    return ((uint32_t)__bfloat16_as_ushort(ly) << 16) | __bfloat16_as_ushort(lx);
}

// ===========================================================================
// Pre-split: fp32 -> bf16 hi + bf16 lo. 4 float4 per thread (MLP=4).
// ===========================================================================
__global__ __launch_bounds__(256) void split_bf16(const float* __restrict__ in,
                                                  __nv_bfloat16* __restrict__ hi,
                                                  __nv_bfloat16* __restrict__ lo,
                                                  int n4) {
    const int i0 = blockIdx.x * 1024 + threadIdx.x;
    float4 v[4];
#pragma unroll
    for (int k = 0; k < 4; ++k) {
        const int i = i0 + k * 256;
        if (i < n4) v[k] = ((const float4*)in)[i];
    }
#pragma unroll
    for (int k = 0; k < 4; ++k) {
        const int i = i0 + k * 256;
        if (i < n4) {
            uint2 ph, pl;
            ph.x = pack_hi2(v[k].x, v[k].y);  ph.y = pack_hi2(v[k].z, v[k].w);
            pl.x = pack_lo2(v[k].x, v[k].y);  pl.y = pack_lo2(v[k].z, v[k].w);
            ((uint2*)hi)[i] = ph;
            ((uint2*)lo)[i] = pl;
        }
    }
}

__global__ __launch_bounds__(256) void split_w4(const float* __restrict__ w0,
                                                const float* __restrict__ w1,
                                                const float* __restrict__ w2,
                                                const float* __restrict__ w3,
                                                __nv_bfloat16* __restrict__ hi,
                                                __nv_bfloat16* __restrict__ lo,
                                                int n4each) {
    const int i0 = blockIdx.x * 1024 + threadIdx.x;
    const int ntot = 4 * n4each;
    float4 v[4];
#pragma unroll
    for (int k = 0; k < 4; ++k) {
        const int i = i0 + k * 256;
        if (i < ntot) {
            const int w = i / n4each, j = i - w * n4each;
            const float* src = (w == 0) ? w0 : (w == 1) ? w1 : (w == 2) ? w2 : w3;
            v[k] = ((const float4*)src)[j];
        }
    }
#pragma unroll
    for (int k = 0; k < 4; ++k) {
        const int i = i0 + k * 256;
        if (i < ntot) {
            uint2 ph, pl;
            ph.x = pack_hi2(v[k].x, v[k].y);  ph.y = pack_hi2(v[k].z, v[k].w);
            pl.x = pack_lo2(v[k].x, v[k].y);  pl.y = pack_lo2(v[k].z, v[k].w);
            ((uint2*)hi)[i] = ph;
            ((uint2*)lo)[i] = pl;
        }
    }
}

// ===========================================================================
// GEMM core: 128x128 tile, bf16 3-term split, 3-stage cp.async pipeline,
// one __syncthreads per k-chunk (unchanged R12 version).
// ===========================================================================
constexpr int NKC = Dm / 32;          // 32 k-chunks
constexpr int GEMM_SMEM = 3 * 32768;  // 98304

__device__ __forceinline__ uint32_t swaddr(uint32_t base, int row, int ch) {
    return base + row * 64 + (((ch) ^ ((row >> 1) & 3)) << 4);
}

__device__ __forceinline__ void gemm_core(
        const __nv_bfloat16* __restrict__ Ah, const __nv_bfloat16* __restrict__ Al,
        const __nv_bfloat16* __restrict__ Bh, const __nv_bfloat16* __restrict__ Bl,
        float* __restrict__ C, int row0, int col0, uint32_t smb) {
    const int tid = threadIdx.x;
    const int lane = tid & 31;
    const int wid = tid >> 5;
    const int wm = (wid >> 2) * 64;
    const int wn = (wid & 3) * 32;
    const int group = lane >> 2, tig = lane & 3;

    float c[4][4][4];
#pragma unroll
    for (int i = 0; i < 4; ++i)
#pragma unroll
        for (int j = 0; j < 4; ++j)
#pragma unroll
            for (int r = 0; r < 4; ++r) c[i][j][r] = 0.f;

    auto issue = [&](int kc, int s) {
        const uint32_t base = smb + s * 32768;
#pragma unroll
        for (int i = 0; i < 2; ++i) {
            const int cidx = tid + i * 256;
            const int row = cidx >> 2, ch = cidx & 3;
            const size_t ga = (size_t)(row0 + row) * Dm + kc * 32 + ch * 8;
            const size_t gb = (size_t)(col0 + row) * Dm + kc * 32 + ch * 8;
            CP_ASYNC16(swaddr(base,         row, ch), Ah + ga);
            CP_ASYNC16(swaddr(base + 8192,  row, ch), Al + ga);
            CP_ASYNC16(swaddr(base + 16384, row, ch), Bh + gb);
            CP_ASYNC16(swaddr(base + 24576, row, ch), Bl + gb);
        }
    };

    issue(0, 0); CP_COMMIT();
    issue(1, 1); CP_COMMIT();

    for (int kc = 0; kc < NKC; ++kc) {
        if (kc + 1 < NKC) { CP_WAIT(1); } else { CP_WAIT(0); }
        __syncthreads();
        if (kc + 2 < NKC) {
            issue(kc + 2, (kc + 2) % 3);
            CP_COMMIT();
        }

        const uint32_t sA = smb + (kc % 3) * 32768;
        const uint32_t sB = sA + 16384;
#pragma unroll
        for (int u = 0; u < 2; ++u) {
            uint32_t bh[8], bl8[8];
#pragma unroll
            for (int p = 0; p < 2; ++p) {
                const int nrow = wn + p * 16 + (lane & 15);
                const int chL = u * 2 + (lane >> 4);
                LDSM4(bh + p * 4,  swaddr(sB,        nrow, chL));
                LDSM4(bl8 + p * 4, swaddr(sB + 8192, nrow, chL));
            }
#pragma unroll
            for (int mt = 0; mt < 4; ++mt) {
                const int mrow = wm + mt * 16 + (lane & 15);
                const int chL = u * 2 + (lane >> 4);
                uint32_t ah[4], alr[4];
                LDSM4(ah,  swaddr(sA,        mrow, chL));
                LDSM4(alr, swaddr(sA + 8192, mrow, chL));
#pragma unroll
                for (int j = 0; j < 4; ++j) {
                    const int p = j >> 1, q = j & 1;
                    MMA_BF16(c[mt][j], ah,  bh[p * 4 + q],  bh[p * 4 + q + 2]);
                    MMA_BF16(c[mt][j], ah,  bl8[p * 4 + q], bl8[p * 4 + q + 2]);
                    MMA_BF16(c[mt][j], alr, bh[p * 4 + q],  bh[p * 4 + q + 2]);
                }
            }
        }
    }

#pragma unroll
    for (int mt = 0; mt < 4; ++mt) {
#pragma unroll
        for (int j = 0; j < 4; ++j) {
            const int r = row0 + wm + mt * 16 + group;
            const int col = col0 + wn + j * 8 + tig * 2;
            float2 v0 = make_float2(c[mt][j][0], c[mt][j][1]);
            float2 v1 = make_float2(c[mt][j][2], c[mt][j][3]);
            *(float2*)(C + (size_t)r * Dm + col)       = v0;
            *(float2*)(C + (size_t)(r + 8) * Dm + col) = v1;
        }
    }
}

__global__ __launch_bounds__(256, 2) void gemm_qkv(
        const __nv_bfloat16* __restrict__ xh, const __nv_bfloat16* __restrict__ xl,
        const __nv_bfloat16* __restrict__ Wh, const __nv_bfloat16* __restrict__ Wl,
        float* __restrict__ Q, float* __restrict__ K, float* __restrict__ V) {
    extern __shared__ char smc[];
    const int z = blockIdx.z;
    const size_t WN = (size_t)Dm * Dm;
    float* C = (z == 0) ? Q : (z == 1) ? K : V;
    gemm_core(xh, xl, Wh + z * WN, Wl + z * WN, C,
              blockIdx.y * 128, blockIdx.x * 128, smem_u32(smc));
}

__global__ __launch_bounds__(256, 2) void gemm_sp(
        const __nv_bfloat16* __restrict__ Ah, const __nv_bfloat16* __restrict__ Al,
        const __nv_bfloat16* __restrict__ Bh, const __nv_bfloat16* __restrict__ Bl,
        float* __restrict__ C) {
    extern __shared__ char smc[];
    gemm_core(Ah, Al, Bh, Bl, C, blockIdx.y * 128, blockIdx.x * 128,
              smem_u32(smc));
}

// ===========================================================================
// Flash attention: 128 threads, 4 warps x 32 q-rows each (two 16-row halves).
// Every K/V smem fragment is reused by TWO MMAs (halves r=0,1):
// MMA:LDS ratio doubles vs the 16-row/warp version. Same numerics per row.
// tf32 mma.sync, 3-stage cp.async, one barrier per tile, shuffle-free P
// relayout (S col 2t = PV k t, col 2t+1 = k t+4; C frag == A frag; V rows
// read permuted). K/V stride 68, scalar LDS.
// ===========================================================================
constexpr int FST = 68;
constexpr int FTILE_B = 64 * FST * 4 * 2;          // 34816 bytes per stage
constexpr int ATT_SMEM = 3 * FTILE_B;              // 104448
constexpr int NT_ = S_ / 64;                       // 32 tiles

__global__ __launch_bounds__(128, 2) void flash_tf32(
        const float* __restrict__ Q, const float* __restrict__ K,
        const float* __restrict__ V,
        __nv_bfloat16* __restrict__ OH, __nv_bfloat16* __restrict__ OL) {
    extern __shared__ float smf[];
    const uint32_t smb = smem_u32(smf);

    const int tid = threadIdx.x;
    const int lane = tid & 31;
    const int wid = tid >> 5;              // 0..3
    const int group = lane >> 2, tig = lane & 3;
    const int q0 = blockIdx.x * 128;
    const int h = blockIdx.y;
    const int b = blockIdx.z;
    const int wb = wid * 32;               // 32 q-rows per warp

    const float* Kb = K + ((size_t)(b * S_)) * Dm + h * DK_;
    const float* Vb = V + ((size_t)(b * S_)) * Dm + h * DK_;

    auto issue = [&](int kt, int s) {
        const uint32_t kbase = smb + s * FTILE_B;
        const uint32_t vbase = kbase + 64 * FST * 4;
#pragma unroll
        for (int i = 0; i < 8; ++i) {
            const int id = tid + i * 128;          // 0..1023
            const int r = id >> 4, ch = id & 15;
            const size_t g = (size_t)(kt * 64 + r) * Dm + ch * 4;
            CP_ASYNC16(kbase + r * (FST * 4) + ch * 16, Kb + g);
            CP_ASYNC16(vbase + r * (FST * 4) + ch * 16, Vb + g);
        }
    };

    issue(0, 0); CP_COMMIT();
    issue(1, 1); CP_COMMIT();

    // Q fragments for both 16-row halves (scaled + tf32-rna)
    uint32_t qf[2][8][4];
    {
        const float* Qb = Q + ((size_t)(b * S_ + q0 + wb)) * Dm + h * DK_;
#pragma unroll
        for (int r = 0; r < 2; ++r) {
#pragma unroll
            for (int ks = 0; ks < 8; ++ks) {
                const int k0 = ks * 8 + tig;
                const size_t r0 = (size_t)(r * 16 + group) * Dm;
                const size_t r1 = (size_t)(r * 16 + group + 8) * Dm;
                qf[r][ks][0] = f2tf(Qb[r0 + k0] * ATT_SCALE);
                qf[r][ks][1] = f2tf(Qb[r1 + k0] * ATT_SCALE);
                qf[r][ks][2] = f2tf(Qb[r0 + k0 + 4] * ATT_SCALE);
                qf[r][ks][3] = f2tf(Qb[r1 + k0 + 4] * ATT_SCALE);
            }
        }
    }

    float of[2][8][4];
#pragma unroll
    for (int r = 0; r < 2; ++r)
#pragma unroll
        for (int nt = 0; nt < 8; ++nt)
#pragma unroll
            for (int q = 0; q < 4; ++q) of[r][nt][q] = 0.f;
    float mr[2][2] = {{-1e30f, -1e30f}, {-1e30f, -1e30f}};
    float lr[2][2] = {{0.f, 0.f}, {0.f, 0.f}};

    for (int kt = 0; kt < NT_; ++kt) {
        if (kt + 1 < NT_) { CP_WAIT(1); } else { CP_WAIT(0); }
        __syncthreads();
        if (kt + 2 < NT_) {
            issue(kt + 2, (kt + 2) % 3);
            CP_COMMIT();
        }

        const float* Ksc = smf + (kt % 3) * (FTILE_B / 4);
        const float* Vsc = Ksc + 64 * FST;

        // S = Q K^T for both halves; each K fragment feeds 2 MMAs
        float sf[2][8][4];
#pragma unroll
        for (int r = 0; r < 2; ++r)
#pragma unroll
            for (int nt = 0; nt < 8; ++nt)
#pragma unroll
                for (int q = 0; q < 4; ++q) sf[r][nt][q] = 0.f;
#pragma unroll
        for (int nt = 0; nt < 8; ++nt) {
            const float* krow = Ksc + (nt * 8 + group) * FST;
#pragma unroll
            for (int ks = 0; ks < 8; ++ks) {
                const uint32_t b0 = f_as_u(krow[ks * 8 + tig]);
                const uint32_t b1 = f_as_u(krow[ks * 8 + tig + 4]);
                MMA_TF32(sf[0][nt], qf[0][ks], b0, b1);
                MMA_TF32(sf[1][nt], qf[1][ks], b0, b1);
            }
        }

        // online softmax per half
        float al[2][2];
#pragma unroll
        for (int r = 0; r < 2; ++r) {
            float mx0 = -1e30f, mx1 = -1e30f;
#pragma unroll
            for (int nt = 0; nt < 8; ++nt) {
                mx0 = fmaxf(mx0, fmaxf(sf[r][nt][0], sf[r][nt][1]));
                mx1 = fmaxf(mx1, fmaxf(sf[r][nt][2], sf[r][nt][3]));
            }
            mx0 = fmaxf(mx0, __shfl_xor_sync(0xffffffffu, mx0, 1));
            mx0 = fmaxf(mx0, __shfl_xor_sync(0xffffffffu, mx0, 2));
            mx1 = fmaxf(mx1, __shfl_xor_sync(0xffffffffu, mx1, 1));
            mx1 = fmaxf(mx1, __shfl_xor_sync(0xffffffffu, mx1, 2));
            const float M0 = fmaxf(mr[r][0], mx0), M1 = fmaxf(mr[r][1], mx1);
            al[r][0] = __expf(mr[r][0] - M0);
            al[r][1] = __expf(mr[r][1] - M1);
            float s0 = 0.f, s1 = 0.f;
#pragma unroll
            for (int nt = 0; nt < 8; ++nt) {
                sf[r][nt][0] = __expf(sf[r][nt][0] - M0);
                sf[r][nt][1] = __expf(sf[r][nt][1] - M0);
                sf[r][nt][2] = __expf(sf[r][nt][2] - M1);
                sf[r][nt][3] = __expf(sf[r][nt][3] - M1);
                s0 += sf[r][nt][0] + sf[r][nt][1];
                s1 += sf[r][nt][2] + sf[r][nt][3];
            }
            s0 += __shfl_xor_sync(0xffffffffu, s0, 1);
            s0 += __shfl_xor_sync(0xffffffffu, s0, 2);
            s1 += __shfl_xor_sync(0xffffffffu, s1, 1);
            s1 += __shfl_xor_sync(0xffffffffu, s1, 2);
            lr[r][0] = lr[r][0] * al[r][0] + s0;  mr[r][0] = M0;
            lr[r][1] = lr[r][1] * al[r][1] + s1;  mr[r][1] = M1;
        }

        // rescale O, then O += P V; each V fragment feeds 2 MMAs
#pragma unroll
        for (int r = 0; r < 2; ++r)
#pragma unroll
            for (int nt = 0; nt < 8; ++nt) {
                of[r][nt][0] *= al[r][0]; of[r][nt][1] *= al[r][0];
                of[r][nt][2] *= al[r][1]; of[r][nt][3] *= al[r][1];
            }
#pragma unroll
        for (int ks = 0; ks < 8; ++ks) {
            uint32_t pa[2][4];
#pragma unroll
            for (int r = 0; r < 2; ++r) {
                pa[r][0] = f2tf(sf[r][ks][0]);
                pa[r][1] = f2tf(sf[r][ks][2]);
                pa[r][2] = f2tf(sf[r][ks][1]);
                pa[r][3] = f2tf(sf[r][ks][3]);
            }
            const float* v0row = Vsc + (ks * 8 + 2 * tig) * FST;
            const float* v1row = Vsc + (ks * 8 + 2 * tig + 1) * FST;
#pragma unroll
            for (int nt = 0; nt < 8; ++nt) {
                const uint32_t b0 = f_as_u(v0row[nt * 8 + group]);
                const uint32_t b1 = f_as_u(v1row[nt * 8 + group]);
                MMA_TF32F(of[0][nt], pa[0][0], pa[0][1], pa[0][2], pa[0][3], b0, b1);
                MMA_TF32F(of[1][nt], pa[1][0], pa[1][1], pa[1][2], pa[1][3], b0, b1);
            }
        }
    }

    // epilogue: write O directly as bf16 hi/lo pairs (both halves)
#pragma unroll
    for (int r = 0; r < 2; ++r) {
        const float i0 = 1.f / lr[r][0], i1 = 1.f / lr[r][1];
        const size_t base0 =
            ((size_t)(b * S_ + q0 + wb + r * 16 + group)) * Dm + h * DK_;
        const size_t base1 =
            ((size_t)(b * S_ + q0 + wb + r * 16 + group + 8)) * Dm + h * DK_;
#pragma unroll
        for (int nt = 0; nt < 8; ++nt) {
            const int col = nt * 8 + tig * 2;
            const float v0 = of[r][nt][0] * i0, v1 = of[r][nt][1] * i0;
            const float v2 = of[r][nt][2] * i1, v3 = of[r][nt][3] * i1;
            *(uint32_t*)(OH + base0 + col) = pack_hi2(v0, v1);
            *(uint32_t*)(OL + base0 + col) = pack_lo2(v0, v1);
            *(uint32_t*)(OH + base1 + col) = pack_hi2(v2, v3);
            *(uint32_t*)(OL + base1 + col) = pack_lo2(v2, v3);
        }
    }
}

// ===========================================================================
extern "C" void kernel_launch(void* const* d_in, const int* in_sizes, int n_in,
                              void* d_out, int out_size) {
    const float* x  = (const float*)d_in[0];
    const float* Wq = (const float*)d_in[1];
    const float* Wk = (const float*)d_in[2];
    const float* Wv = (const float*)d_in[3];
    const float* Wo = (const float*)d_in[4];
    float* out = (float*)d_out;

    float *Qp, *Kp, *Vp;
    __nv_bfloat16 *xh, *xl, *oh, *ol, *wh, *wl;
    cudaGetSymbolAddress((void**)&Qp, g_Q);
    cudaGetSymbolAddress((void**)&Kp, g_K);
    cudaGetSymbolAddress((void**)&Vp, g_V);
    cudaGetSymbolAddress((void**)&xh, g_xh);
    cudaGetSymbolAddress((void**)&xl, g_xl);
    cudaGetSymbolAddress((void**)&oh, g_oh);
    cudaGetSymbolAddress((void**)&ol, g_ol);
    cudaGetSymbolAddress((void**)&wh, g_wh);
    cudaGetSymbolAddress((void**)&wl, g_wl);

    cudaFuncSetAttribute(gemm_qkv, cudaFuncAttributeMaxDynamicSharedMemorySize,
                         GEMM_SMEM);
    cudaFuncSetAttribute(gemm_sp, cudaFuncAttributeMaxDynamicSharedMemorySize,
                         GEMM_SMEM);
    cudaFuncSetAttribute(flash_tf32, cudaFuncAttributeMaxDynamicSharedMemorySize,
                         ATT_SMEM);

    const size_t WN = (size_t)Dm * Dm;  // 1M elements per W
    const int n4x = (Mrows * Dm) / 4;   // 1M float4
    const int n4w = (int)(WN / 4);      // 256K float4

    split_bf16<<<(n4x + 1023) / 1024, 256>>>(x, xh, xl, n4x);
    split_w4<<<(4 * n4w + 1023) / 1024, 256>>>(Wq, Wk, Wv, Wo, wh, wl, n4w);

    const dim3 gQKV(Dm / 128, Mrows / 128, 3);    // (8, 32, 3)
    gemm_qkv<<<gQKV, 256, GEMM_SMEM>>>(xh, xl, wh, wl, Qp, Kp, Vp);

    const dim3 gAttn(S_ / 128, H_, B_);           // (16, 16, 2)
    flash_tf32<<<gAttn, 128, ATT_SMEM>>>(Qp, Kp, Vp, oh, ol);

    const dim3 gProj(Dm / 128, Mrows / 128);      // (8, 32)
    gemm_sp<<<gProj, 256, GEMM_SMEM>>>(oh, ol, wh + 3 * WN, wl + 3 * WN, out);
}

// round 14
// speedup vs baseline: 1.6220x; 1.5175x over previous
#include <cuda_runtime.h>
#include <cuda_fp16.h>
#include <cstdint>

// ===========================================================================
// Problem constants
// ===========================================================================
constexpr int B_   = 2;
constexpr int S_   = 2048;
constexpr int Dm   = 1024;
constexpr int H_   = 16;
constexpr int DK_  = 64;
constexpr int Mrows = B_ * S_;        // 4096
constexpr float ATT_SCALE = 0.125f;   // 1/sqrt(64)

// Scratch (allocation-free: __device__ globals)
__device__ float  g_Q[(size_t)Mrows * Dm];
__device__ float  g_K[(size_t)Mrows * Dm];
__device__ float  g_V[(size_t)Mrows * Dm];
__device__ __half g_xh[(size_t)Mrows * Dm];
__device__ __half g_oh[(size_t)Mrows * Dm];
__device__ __half g_wh[(size_t)4 * Dm * Dm];

// ===========================================================================
// mma.sync / ldmatrix / cp.async helpers (legacy tensor path, sm_103 base)
// ===========================================================================
#define MMA_F16(c, a, b0, b1)                                               \
    asm volatile(                                                           \
        "mma.sync.aligned.m16n8k16.row.col.f32.f16.f16.f32 "                \
        "{%0,%1,%2,%3},{%4,%5,%6,%7},{%8,%9},{%0,%1,%2,%3};"                \
        : "+f"((c)[0]), "+f"((c)[1]), "+f"((c)[2]), "+f"((c)[3])            \
        : "r"((a)[0]), "r"((a)[1]), "r"((a)[2]), "r"((a)[3]),               \
          "r"(b0), "r"(b1))

#define MMA_TF32(c, a, b0, b1)                                              \
    asm volatile(                                                           \
        "mma.sync.aligned.m16n8k8.row.col.f32.tf32.tf32.f32 "               \
        "{%0,%1,%2,%3},{%4,%5,%6,%7},{%8,%9},{%0,%1,%2,%3};"                \
        : "+f"((c)[0]), "+f"((c)[1]), "+f"((c)[2]), "+f"((c)[3])            \
        : "r"((a)[0]), "r"((a)[1]), "r"((a)[2]), "r"((a)[3]),               \
          "r"(b0), "r"(b1))

// tf32 MMA where A comes in as raw uint regs (accumulator reinterpret)
#define MMA_TF32F(c, a0, a1, a2, a3, b0, b1)                                \
    asm volatile(                                                           \
        "mma.sync.aligned.m16n8k8.row.col.f32.tf32.tf32.f32 "               \
        "{%0,%1,%2,%3},{%4,%5,%6,%7},{%8,%9},{%0,%1,%2,%3};"                \
        : "+f"((c)[0]), "+f"((c)[1]), "+f"((c)[2]), "+f"((c)[3])            \
        : "r"(a0), "r"(a1), "r"(a2), "r"(a3), "r"(b0), "r"(b1))

#define LDSM4(R, addr)                                                      \
    asm volatile("ldmatrix.sync.aligned.m8n8.x4.shared.b16 "                \
                 "{%0,%1,%2,%3}, [%4];"                                     \
                 : "=r"((R)[0]), "=r"((R)[1]), "=r"((R)[2]), "=r"((R)[3])   \
                 : "r"(addr))

#define CP_ASYNC16(dst, src)                                                \
    asm volatile("cp.async.cg.shared.global [%0], [%1], 16;"                \
                 :: "r"(dst), "l"(src))
#define CP_COMMIT() asm volatile("cp.async.commit_group;" ::: "memory")
#define CP_WAIT(n)  asm volatile("cp.async.wait_group %0;" :: "n"(n) : "memory")

__device__ __forceinline__ uint32_t smem_u32(const void* p) {
    uint32_t a;
    asm("{ .reg .u64 t; cvta.to.shared.u64 t, %1; cvt.u32.u64 %0, t; }"
        : "=r"(a) : "l"(p));
    return a;
}
__device__ __forceinline__ uint32_t f2tf(float x) {
    uint32_t r;
    asm("cvt.rna.tf32.f32 %0, %1;" : "=r"(r) : "f"(x));
    return r;
}
__device__ __forceinline__ float u2f(uint32_t x) { return __uint_as_float(x); }
__device__ __forceinline__ uint32_t f_as_u(float x) { return __float_as_uint(x); }

__device__ __forceinline__ uint32_t pack_h2(float x, float y) {
    __half2 h = __halves2half2(__float2half_rn(x), __float2half_rn(y));
    return *(uint32_t*)&h;
}

// ===========================================================================
// Pre-split: fp32 -> fp16. 4 float4 per thread (MLP=4).
// ===========================================================================
__global__ __launch_bounds__(256) void split_f16(const float* __restrict__ in,
                                                 __half* __restrict__ hi,
                                                 int n4) {
    const int i0 = blockIdx.x * 1024 + threadIdx.x;
    float4 v[4];
#pragma unroll
    for (int k = 0; k < 4; ++k) {
        const int i = i0 + k * 256;
        if (i < n4) v[k] = ((const float4*)in)[i];
    }
#pragma unroll
    for (int k = 0; k < 4; ++k) {
        const int i = i0 + k * 256;
        if (i < n4) {
            uint2 ph;
            ph.x = pack_h2(v[k].x, v[k].y);
            ph.y = pack_h2(v[k].z, v[k].w);
            ((uint2*)hi)[i] = ph;
        }
    }
}

__global__ __launch_bounds__(256) void split_w4(const float* __restrict__ w0,
                                                const float* __restrict__ w1,
                                                const float* __restrict__ w2,
                                                const float* __restrict__ w3,
                                                __half* __restrict__ hi,
                                                int n4each) {
    const int i0 = blockIdx.x * 1024 + threadIdx.x;
    const int ntot = 4 * n4each;
    float4 v[4];
#pragma unroll
    for (int k = 0; k < 4; ++k) {
        const int i = i0 + k * 256;
        if (i < ntot) {
            const int w = i / n4each, j = i - w * n4each;
            const float* src = (w == 0) ? w0 : (w == 1) ? w1 : (w == 2) ? w2 : w3;
            v[k] = ((const float4*)src)[j];
        }
    }
#pragma unroll
    for (int k = 0; k < 4; ++k) {
        const int i = i0 + k * 256;
        if (i < ntot) {
            uint2 ph;
            ph.x = pack_h2(v[k].x, v[k].y);
            ph.y = pack_h2(v[k].z, v[k].w);
            ((uint2*)hi)[i] = ph;
        }
    }
}

// ===========================================================================
// GEMM core: 128x128 tile, fp16 single-pass mma.sync, 3-stage cp.async,
// one __syncthreads per k-chunk. Stage = A 8KB + B 8KB = 16KB; x3 = 48KB.
// ===========================================================================
constexpr int NKC = Dm / 32;          // 32 k-chunks
constexpr int GEMM_SMEM = 3 * 16384;  // 49152

__device__ __forceinline__ uint32_t swaddr(uint32_t base, int row, int ch) {
    return base + row * 64 + (((ch) ^ ((row >> 1) & 3)) << 4);
}

__device__ __forceinline__ void gemm_core(
        const __half* __restrict__ Ah, const __half* __restrict__ Bh,
        float* __restrict__ C, int row0, int col0, uint32_t smb) {
    const int tid = threadIdx.x;
    const int lane = tid & 31;
    const int wid = tid >> 5;
    const int wm = (wid >> 2) * 64;
    const int wn = (wid & 3) * 32;
    const int group = lane >> 2, tig = lane & 3;

    float c[4][4][4];
#pragma unroll
    for (int i = 0; i < 4; ++i)
#pragma unroll
        for (int j = 0; j < 4; ++j)
#pragma unroll
            for (int r = 0; r < 4; ++r) c[i][j][r] = 0.f;

    auto issue = [&](int kc, int s) {
        const uint32_t base = smb + s * 16384;
#pragma unroll
        for (int i = 0; i < 2; ++i) {
            const int cidx = tid + i * 256;      // 0..511
            const int row = cidx >> 2, ch = cidx & 3;
            const size_t ga = (size_t)(row0 + row) * Dm + kc * 32 + ch * 8;
            const size_t gb = (size_t)(col0 + row) * Dm + kc * 32 + ch * 8;
            CP_ASYNC16(swaddr(base,        row, ch), Ah + ga);
            CP_ASYNC16(swaddr(base + 8192, row, ch), Bh + gb);
        }
    };

    issue(0, 0); CP_COMMIT();
    issue(1, 1); CP_COMMIT();

    for (int kc = 0; kc < NKC; ++kc) {
        if (kc + 1 < NKC) { CP_WAIT(1); } else { CP_WAIT(0); }
        __syncthreads();
        if (kc + 2 < NKC) {
            issue(kc + 2, (kc + 2) % 3);
            CP_COMMIT();
        }

        const uint32_t sA = smb + (kc % 3) * 16384;
        const uint32_t sB = sA + 8192;
#pragma unroll
        for (int u = 0; u < 2; ++u) {
            uint32_t bh[8];
#pragma unroll
            for (int p = 0; p < 2; ++p) {
                const int nrow = wn + p * 16 + (lane & 15);
                const int chL = u * 2 + (lane >> 4);
                LDSM4(bh + p * 4, swaddr(sB, nrow, chL));
            }
#pragma unroll
            for (int mt = 0; mt < 4; ++mt) {
                const int mrow = wm + mt * 16 + (lane & 15);
                const int chL = u * 2 + (lane >> 4);
                uint32_t ah[4];
                LDSM4(ah, swaddr(sA, mrow, chL));
#pragma unroll
                for (int j = 0; j < 4; ++j) {
                    const int p = j >> 1, q = j & 1;
                    MMA_F16(c[mt][j], ah, bh[p * 4 + q], bh[p * 4 + q + 2]);
                }
            }
        }
    }

#pragma unroll
    for (int mt = 0; mt < 4; ++mt) {
#pragma unroll
        for (int j = 0; j < 4; ++j) {
            const int r = row0 + wm + mt * 16 + group;
            const int col = col0 + wn + j * 8 + tig * 2;
            float2 v0 = make_float2(c[mt][j][0], c[mt][j][1]);
            float2 v1 = make_float2(c[mt][j][2], c[mt][j][3]);
            *(float2*)(C + (size_t)r * Dm + col)       = v0;
            *(float2*)(C + (size_t)(r + 8) * Dm + col) = v1;
        }
    }
}

__global__ __launch_bounds__(256, 2) void gemm_qkv(
        const __half* __restrict__ xh, const __half* __restrict__ Wh,
        float* __restrict__ Q, float* __restrict__ K, float* __restrict__ V) {
    extern __shared__ char smc[];
    const int z = blockIdx.z;
    const size_t WN = (size_t)Dm * Dm;
    float* C = (z == 0) ? Q : (z == 1) ? K : V;
    gemm_core(xh, Wh + z * WN, C, blockIdx.y * 128, blockIdx.x * 128,
              smem_u32(smc));
}

__global__ __launch_bounds__(256, 2) void gemm_sp(
        const __half* __restrict__ Ah, const __half* __restrict__ Bh,
        float* __restrict__ C) {
    extern __shared__ char smc[];
    gemm_core(Ah, Bh, C, blockIdx.y * 128, blockIdx.x * 128, smem_u32(smc));
}

// ===========================================================================
// Flash attention (R13 structure): 128 threads, 4 warps x 32 q-rows (two
// 16-row halves; K/V fragments reused by both). tf32 mma.sync, 3-stage
// cp.async, one barrier per tile, shuffle-free P relayout. Epilogue writes
// O directly as fp16 (single array).
// ===========================================================================
constexpr int FST = 68;
constexpr int FTILE_B = 64 * FST * 4 * 2;          // 34816 bytes per stage
constexpr int ATT_SMEM = 3 * FTILE_B;              // 104448
constexpr int NT_ = S_ / 64;                       // 32 tiles

__global__ __launch_bounds__(128, 2) void flash_tf32(
        const float* __restrict__ Q, const float* __restrict__ K,
        const float* __restrict__ V, __half* __restrict__ OH) {
    extern __shared__ float smf[];
    const uint32_t smb = smem_u32(smf);

    const int tid = threadIdx.x;
    const int lane = tid & 31;
    const int wid = tid >> 5;              // 0..3
    const int group = lane >> 2, tig = lane & 3;
    const int q0 = blockIdx.x * 128;
    const int h = blockIdx.y;
    const int b = blockIdx.z;
    const int wb = wid * 32;               // 32 q-rows per warp

    const float* Kb = K + ((size_t)(b * S_)) * Dm + h * DK_;
    const float* Vb = V + ((size_t)(b * S_)) * Dm + h * DK_;

    auto issue = [&](int kt, int s) {
        const uint32_t kbase = smb + s * FTILE_B;
        const uint32_t vbase = kbase + 64 * FST * 4;
#pragma unroll
        for (int i = 0; i < 8; ++i) {
            const int id = tid + i * 128;          // 0..1023
            const int r = id >> 4, ch = id & 15;
            const size_t g = (size_t)(kt * 64 + r) * Dm + ch * 4;
            CP_ASYNC16(kbase + r * (FST * 4) + ch * 16, Kb + g);
            CP_ASYNC16(vbase + r * (FST * 4) + ch * 16, Vb + g);
        }
    };

    issue(0, 0); CP_COMMIT();
    issue(1, 1); CP_COMMIT();

    // Q fragments for both 16-row halves (scaled + tf32-rna)
    uint32_t qf[2][8][4];
    {
        const float* Qb = Q + ((size_t)(b * S_ + q0 + wb)) * Dm + h * DK_;
#pragma unroll
        for (int r = 0; r < 2; ++r) {
#pragma unroll
            for (int ks = 0; ks < 8; ++ks) {
                const int k0 = ks * 8 + tig;
                const size_t r0 = (size_t)(r * 16 + group) * Dm;
                const size_t r1 = (size_t)(r * 16 + group + 8) * Dm;
                qf[r][ks][0] = f2tf(Qb[r0 + k0] * ATT_SCALE);
                qf[r][ks][1] = f2tf(Qb[r1 + k0] * ATT_SCALE);
                qf[r][ks][2] = f2tf(Qb[r0 + k0 + 4] * ATT_SCALE);
                qf[r][ks][3] = f2tf(Qb[r1 + k0 + 4] * ATT_SCALE);
            }
        }
    }

    float of[2][8][4];
#pragma unroll
    for (int r = 0; r < 2; ++r)
#pragma unroll
        for (int nt = 0; nt < 8; ++nt)
#pragma unroll
            for (int q = 0; q < 4; ++q) of[r][nt][q] = 0.f;
    float mr[2][2] = {{-1e30f, -1e30f}, {-1e30f, -1e30f}};
    float lr[2][2] = {{0.f, 0.f}, {0.f, 0.f}};

    for (int kt = 0; kt < NT_; ++kt) {
        if (kt + 1 < NT_) { CP_WAIT(1); } else { CP_WAIT(0); }
        __syncthreads();
        if (kt + 2 < NT_) {
            issue(kt + 2, (kt + 2) % 3);
            CP_COMMIT();
        }

        const float* Ksc = smf + (kt % 3) * (FTILE_B / 4);
        const float* Vsc = Ksc + 64 * FST;

        // S = Q K^T for both halves; each K fragment feeds 2 MMAs
        float sf[2][8][4];
#pragma unroll
        for (int r = 0; r < 2; ++r)
#pragma unroll
            for (int nt = 0; nt < 8; ++nt)
#pragma unroll
                for (int q = 0; q < 4; ++q) sf[r][nt][q] = 0.f;
#pragma unroll
        for (int nt = 0; nt < 8; ++nt) {
            const float* krow = Ksc + (nt * 8 + group) * FST;
#pragma unroll
            for (int ks = 0; ks < 8; ++ks) {
                const uint32_t b0 = f_as_u(krow[ks * 8 + tig]);
                const uint32_t b1 = f_as_u(krow[ks * 8 + tig + 4]);
                MMA_TF32(sf[0][nt], qf[0][ks], b0, b1);
                MMA_TF32(sf[1][nt], qf[1][ks], b0, b1);
            }
        }

        // online softmax per half
        float al[2][2];
#pragma unroll
        for (int r = 0; r < 2; ++r) {
            float mx0 = -1e30f, mx1 = -1e30f;
#pragma unroll
            for (int nt = 0; nt < 8; ++nt) {
                mx0 = fmaxf(mx0, fmaxf(sf[r][nt][0], sf[r][nt][1]));
                mx1 = fmaxf(mx1, fmaxf(sf[r][nt][2], sf[r][nt][3]));
            }
            mx0 = fmaxf(mx0, __shfl_xor_sync(0xffffffffu, mx0, 1));
            mx0 = fmaxf(mx0, __shfl_xor_sync(0xffffffffu, mx0, 2));
            mx1 = fmaxf(mx1, __shfl_xor_sync(0xffffffffu, mx1, 1));
            mx1 = fmaxf(mx1, __shfl_xor_sync(0xffffffffu, mx1, 2));
            const float M0 = fmaxf(mr[r][0], mx0), M1 = fmaxf(mr[r][1], mx1);
            al[r][0] = __expf(mr[r][0] - M0);
            al[r][1] = __expf(mr[r][1] - M1);
            float s0 = 0.f, s1 = 0.f;
#pragma unroll
            for (int nt = 0; nt < 8; ++nt) {
                sf[r][nt][0] = __expf(sf[r][nt][0] - M0);
                sf[r][nt][1] = __expf(sf[r][nt][1] - M0);
                sf[r][nt][2] = __expf(sf[r][nt][2] - M1);
                sf[r][nt][3] = __expf(sf[r][nt][3] - M1);
                s0 += sf[r][nt][0] + sf[r][nt][1];
                s1 += sf[r][nt][2] + sf[r][nt][3];
            }
            s0 += __shfl_xor_sync(0xffffffffu, s0, 1);
            s0 += __shfl_xor_sync(0xffffffffu, s0, 2);
            s1 += __shfl_xor_sync(0xffffffffu, s1, 1);
            s1 += __shfl_xor_sync(0xffffffffu, s1, 2);
            lr[r][0] = lr[r][0] * al[r][0] + s0;  mr[r][0] = M0;
            lr[r][1] = lr[r][1] * al[r][1] + s1;  mr[r][1] = M1;
        }

        // rescale O, then O += P V; each V fragment feeds 2 MMAs
#pragma unroll
        for (int r = 0; r < 2; ++r)
#pragma unroll
            for (int nt = 0; nt < 8; ++nt) {
                of[r][nt][0] *= al[r][0]; of[r][nt][1] *= al[r][0];
                of[r][nt][2] *= al[r][1]; of[r][nt][3] *= al[r][1];
            }
#pragma unroll
        for (int ks = 0; ks < 8; ++ks) {
            uint32_t pa[2][4];
#pragma unroll
            for (int r = 0; r < 2; ++r) {
                pa[r][0] = f2tf(sf[r][ks][0]);
                pa[r][1] = f2tf(sf[r][ks][2]);
                pa[r][2] = f2tf(sf[r][ks][1]);
                pa[r][3] = f2tf(sf[r][ks][3]);
            }
            const float* v0row = Vsc + (ks * 8 + 2 * tig) * FST;
            const float* v1row = Vsc + (ks * 8 + 2 * tig + 1) * FST;
#pragma unroll
            for (int nt = 0; nt < 8; ++nt) {
                const uint32_t b0 = f_as_u(v0row[nt * 8 + group]);
                const uint32_t b1 = f_as_u(v1row[nt * 8 + group]);
                MMA_TF32F(of[0][nt], pa[0][0], pa[0][1], pa[0][2], pa[0][3], b0, b1);
                MMA_TF32F(of[1][nt], pa[1][0], pa[1][1], pa[1][2], pa[1][3], b0, b1);
            }
        }
    }

    // epilogue: write O directly as fp16 pairs (both halves)
#pragma unroll
    for (int r = 0; r < 2; ++r) {
        const float i0 = 1.f / lr[r][0], i1 = 1.f / lr[r][1];
        const size_t base0 =
            ((size_t)(b * S_ + q0 + wb + r * 16 + group)) * Dm + h * DK_;
        const size_t base1 =
            ((size_t)(b * S_ + q0 + wb + r * 16 + group + 8)) * Dm + h * DK_;
#pragma unroll
        for (int nt = 0; nt < 8; ++nt) {
            const int col = nt * 8 + tig * 2;
            *(uint32_t*)(OH + base0 + col) =
                pack_h2(of[r][nt][0] * i0, of[r][nt][1] * i0);
            *(uint32_t*)(OH + base1 + col) =
                pack_h2(of[r][nt][2] * i1, of[r][nt][3] * i1);
        }
    }
}

// ===========================================================================
extern "C" void kernel_launch(void* const* d_in, const int* in_sizes, int n_in,
                              void* d_out, int out_size) {
    const float* x  = (const float*)d_in[0];
    const float* Wq = (const float*)d_in[1];
    const float* Wk = (const float*)d_in[2];
    const float* Wv = (const float*)d_in[3];
    const float* Wo = (const float*)d_in[4];
    float* out = (float*)d_out;

    float *Qp, *Kp, *Vp;
    __half *xh, *oh, *wh;
    cudaGetSymbolAddress((void**)&Qp, g_Q);
    cudaGetSymbolAddress((void**)&Kp, g_K);
    cudaGetSymbolAddress((void**)&Vp, g_V);
    cudaGetSymbolAddress((void**)&xh, g_xh);
    cudaGetSymbolAddress((void**)&oh, g_oh);
    cudaGetSymbolAddress((void**)&wh, g_wh);

    cudaFuncSetAttribute(gemm_qkv, cudaFuncAttributeMaxDynamicSharedMemorySize,
                         GEMM_SMEM);
    cudaFuncSetAttribute(gemm_sp, cudaFuncAttributeMaxDynamicSharedMemorySize,
                         GEMM_SMEM);
    cudaFuncSetAttribute(flash_tf32, cudaFuncAttributeMaxDynamicSharedMemorySize,
                         ATT_SMEM);

    const size_t WN = (size_t)Dm * Dm;  // 1M elements per W
    const int n4x = (Mrows * Dm) / 4;   // 1M float4
    const int n4w = (int)(WN / 4);      // 256K float4

    split_f16<<<(n4x + 1023) / 1024, 256>>>(x, xh, n4x);
    split_w4<<<(4 * n4w + 1023) / 1024, 256>>>(Wq, Wk, Wv, Wo, wh, n4w);

    const dim3 gQKV(Dm / 128, Mrows / 128, 3);    // (8, 32, 3)
    gemm_qkv<<<gQKV, 256, GEMM_SMEM>>>(xh, wh, Qp, Kp, Vp);

    const dim3 gAttn(S_ / 128, H_, B_);           // (16, 16, 2)
    flash_tf32<<<gAttn, 128, ATT_SMEM>>>(Qp, Kp, Vp, oh);

    const dim3 gProj(Dm / 128, Mrows / 128);      // (8, 32)
    gemm_sp<<<gProj, 256, GEMM_SMEM>>>(oh, wh + 3 * WN, out);
}